// round 2
// baseline (speedup 1.0000x reference)
#include <cuda_runtime.h>
#include <cstddef>

// ---------------- Problem constants ----------------
#define BB   8
#define NN   1024
#define DIMC 512
#define HH   8
#define DD   64
#define RR   64          // R1 = R2 = R = 64
#define MTOT (BB*NN)     // 8192
#define SCALE_ATT 0.125f // D^-0.5
#define S_CONST 1.0f

// ---------------- Scratch (__device__ globals; no allocation allowed) ----------------
__device__ float g_u    [MTOT*RR];          // x @ CP_U_w^T + b
__device__ float g_u2   [MTOT*RR];          // out @ CP_U_w^T + b
__device__ float g_qkv  [(size_t)MTOT*3*DIMC]; // fused qkv
__device__ float g_att  [(size_t)MTOT*DIMC];   // attention output [b,n,h*D+d]
__device__ float g_CPc  [RR*RR*4];
__device__ float g_Wbig [RR*3*DIMC];        // [r, o] o in [0,1536): q|k|v factors
__device__ float g_Wp   [RR*DIMC];          // proj factor (pre-scaled by S)
__device__ float g_qkvwT[DIMC*3*DIMC];      // qkv_w^T  [512,1536]
__device__ float g_projwT[DIMC*DIMC];       // proj_w^T [512,512]
__device__ float g_UwT  [DIMC*RR];          // CP_U_w^T [512,64]
__device__ float g_bq   [3*DIMC];           // CP_V_b tiled x3
__device__ float g_bp   [DIMC];             // proj_b + S*CP_V_b

// ---------------- Small precompute kernels ----------------
__global__ void transpose_kernel(const float* __restrict__ in, float* __restrict__ out,
                                 int rows, int cols) {
    __shared__ float tile[32][33];
    int c0 = blockIdx.x * 32, r0 = blockIdx.y * 32;
    int tx = threadIdx.x, ty = threadIdx.y;
    #pragma unroll
    for (int i = 0; i < 32; i += 8) {
        int r = r0 + ty + i, c = c0 + tx;
        if (r < rows && c < cols) tile[ty + i][tx] = in[(size_t)r * cols + c];
    }
    __syncthreads();
    #pragma unroll
    for (int i = 0; i < 32; i += 8) {
        int c = c0 + ty + i, r = r0 + tx;
        if (r < rows && c < cols) out[(size_t)c * rows + r] = tile[tx][ty + i];
    }
}

// CPc[i,j,f] = sum_r CP_C[i,j,r] * CP_att[r,f]
__global__ void cpc_kernel(const float* __restrict__ CP_C, const float* __restrict__ CP_att) {
    int idx = blockIdx.x * 256 + threadIdx.x;       // 64*64*4 = 16384
    if (idx >= RR * RR * 4) return;
    int f = idx & 3;
    int ij = idx >> 2;                              // i*64+j
    float s = 0.f;
    #pragma unroll 8
    for (int r = 0; r < RR; r++) s += CP_C[(ij << 6) + r] * CP_att[r * 4 + f];
    g_CPc[idx] = s;                                 // layout [i][j][f]
}

// W_f[r,d] = sum_s CPc[r,s,f] * CP_V_w[d,s]
__global__ void wfac_kernel(const float* __restrict__ CP_V_w) {
    int idx = blockIdx.x * 256 + threadIdx.x;       // 64*2048 = 131072
    int r = idx >> 11;
    int o = idx & 2047;
    int f, d;
    if (o < 3 * DIMC) { f = o >> 9; d = o & 511; }
    else              { f = 3;      d = o - 3 * DIMC; }
    float s = 0.f;
    #pragma unroll 8
    for (int ss = 0; ss < RR; ss++)
        s += g_CPc[((r << 6) + ss) * 4 + f] * CP_V_w[d * RR + ss];
    if (o < 3 * DIMC) g_Wbig[r * (3 * DIMC) + o] = s;
    else              g_Wp[r * DIMC + d] = s * S_CONST;
}

__global__ void bias_kernel(const float* __restrict__ CP_V_b, const float* __restrict__ proj_b) {
    int i = blockIdx.x * 256 + threadIdx.x;
    if (i < 3 * DIMC) g_bq[i] = CP_V_b[i & 511];
    if (i < DIMC)     g_bp[i] = proj_b[i] + S_CONST * CP_V_b[i];
}

// ---------------- Dual-source SGEMM: C = A1@B1 + A2@B2 + bias ----------------
// A row-major [M,K] (stride lda), B row-major [K,N] (row length == N), C row-major [M,N].
// BM=BN=128, BK=8, 256 threads, 8x8 per thread.
__global__ __launch_bounds__(256, 2)
void sgemm_dual(const float* __restrict__ A1, int lda1, const float* __restrict__ B1, int K1,
                const float* __restrict__ A2, int lda2, const float* __restrict__ B2, int K2,
                const float* __restrict__ bias, float* __restrict__ C,
                int M, int N) {
    const int BM = 128, BN = 128, BK = 8;
    __shared__ float As[BK][BM + 4];
    __shared__ float Bs[BK][BN];
    int tid = threadIdx.x;
    int bm0 = blockIdx.y * BM;
    int bn0 = blockIdx.x * BN;
    int tx = tid & 15, ty = tid >> 4;

    float acc[8][8];
    #pragma unroll
    for (int i = 0; i < 8; i++)
        #pragma unroll
        for (int j = 0; j < 8; j++) acc[i][j] = 0.f;

    int a_m = tid >> 1;             // 0..127
    int a_k = (tid & 1) * 4;        // 0 or 4
    int b_k = tid >> 5;             // 0..7
    int b_n = (tid & 31) * 4;       // 0..124

    #pragma unroll 1
    for (int pass = 0; pass < 2; pass++) {
        const float* A = pass ? A2 : A1;
        const float* B = pass ? B2 : B1;
        int K   = pass ? K2   : K1;
        int lda = pass ? lda2 : lda1;
        if (K == 0 || A == nullptr) continue;
        #pragma unroll 1
        for (int k0 = 0; k0 < K; k0 += BK) {
            float4 av = *(const float4*)&A[(size_t)(bm0 + a_m) * lda + k0 + a_k];
            float4 bv = make_float4(0.f, 0.f, 0.f, 0.f);
            if (bn0 + b_n < N)
                bv = *(const float4*)&B[(size_t)(k0 + b_k) * N + bn0 + b_n];
            __syncthreads();
            As[a_k + 0][a_m] = av.x;
            As[a_k + 1][a_m] = av.y;
            As[a_k + 2][a_m] = av.z;
            As[a_k + 3][a_m] = av.w;
            *(float4*)&Bs[b_k][b_n] = bv;
            __syncthreads();
            #pragma unroll
            for (int k = 0; k < BK; k++) {
                float4 a0 = *(const float4*)&As[k][ty * 8];
                float4 a1 = *(const float4*)&As[k][ty * 8 + 4];
                float4 b0 = *(const float4*)&Bs[k][tx * 8];
                float4 b1 = *(const float4*)&Bs[k][tx * 8 + 4];
                float rm[8] = {a0.x, a0.y, a0.z, a0.w, a1.x, a1.y, a1.z, a1.w};
                float rn[8] = {b0.x, b0.y, b0.z, b0.w, b1.x, b1.y, b1.z, b1.w};
                #pragma unroll
                for (int i = 0; i < 8; i++)
                    #pragma unroll
                    for (int j = 0; j < 8; j++)
                        acc[i][j] += rm[i] * rn[j];
            }
        }
    }

    // Epilogue with bias
    #pragma unroll
    for (int i = 0; i < 8; i++) {
        int m = bm0 + ty * 8 + i;
        #pragma unroll
        for (int j4 = 0; j4 < 8; j4 += 4) {
            int n = bn0 + tx * 8 + j4;
            if (n < N) {
                float4 v;
                v.x = acc[i][j4 + 0] + bias[n + 0];
                v.y = acc[i][j4 + 1] + bias[n + 1];
                v.z = acc[i][j4 + 2] + bias[n + 2];
                v.w = acc[i][j4 + 3] + bias[n + 3];
                *(float4*)&C[(size_t)m * N + n] = v;
            }
        }
    }
}

// ---------------- Fused flash-style attention (fp32) ----------------
// grid: (N/128, H, B), block: 128 threads. Each thread owns one q row.
// mask is int32 (bool marshalled as int32 by the harness); nonzero = attend.
__global__ __launch_bounds__(128, 3)
void attn_kernel(const float* __restrict__ qkv, const int* __restrict__ mask,
                 float* __restrict__ out) {
    __shared__ float ks[64 * 64];
    __shared__ float vs[64 * 64];
    __shared__ int msk[64];
    int tid = threadIdx.x;
    int b = blockIdx.z, h = blockIdx.y;
    int row = blockIdx.x * 128 + tid;

    const float* qptr = qkv + ((size_t)(b * NN + row)) * (3 * DIMC) + h * DD;
    float q[DD];
    #pragma unroll
    for (int d = 0; d < DD; d++) q[d] = qptr[d] * SCALE_ATT;

    float m_run = -1e30f, l = 0.f;
    float acc[DD];
    #pragma unroll
    for (int d = 0; d < DD; d++) acc[d] = 0.f;

    #pragma unroll 1
    for (int t = 0; t < NN / 64; t++) {
        int m0 = t * 64;
        // cooperative load of K/V 64x64 tiles (float4, coalesced)
        #pragma unroll
        for (int i = 0; i < 8; i++) {
            int idx = i * 128 + tid;            // 0..1023 float4 slots
            int r = idx >> 4;
            int c = (idx & 15) << 2;
            size_t base = ((size_t)(b * NN + m0 + r)) * (3 * DIMC) + h * DD + c;
            *(float4*)&ks[r * 64 + c] = *(const float4*)&qkv[base + DIMC];
            *(float4*)&vs[r * 64 + c] = *(const float4*)&qkv[base + 2 * DIMC];
        }
        if (tid < 64) msk[tid] = mask[b * NN + m0 + tid];
        __syncthreads();

        #pragma unroll 1
        for (int m = 0; m < 64; m++) {
            if (!msk[m]) continue;
            const float4* kr = (const float4*)&ks[m * 64];
            float s = 0.f;
            #pragma unroll
            for (int dd = 0; dd < 16; dd++) {
                float4 kv = kr[dd];
                s += q[dd * 4 + 0] * kv.x + q[dd * 4 + 1] * kv.y
                   + q[dd * 4 + 2] * kv.z + q[dd * 4 + 3] * kv.w;
            }
            float p;
            if (s > m_run) {
                float sc = __expf(m_run - s);
                m_run = s;
                l *= sc;
                #pragma unroll
                for (int d = 0; d < DD; d++) acc[d] *= sc;
                p = 1.f;
            } else {
                p = __expf(s - m_run);
            }
            l += p;
            const float4* vr = (const float4*)&vs[m * 64];
            #pragma unroll
            for (int dd = 0; dd < 16; dd++) {
                float4 vv = vr[dd];
                acc[dd * 4 + 0] += p * vv.x;
                acc[dd * 4 + 1] += p * vv.y;
                acc[dd * 4 + 2] += p * vv.z;
                acc[dd * 4 + 3] += p * vv.w;
            }
        }
        __syncthreads();
    }

    float inv = 1.0f / l;
    float* op = out + ((size_t)(b * NN + row)) * DIMC + h * DD;
    #pragma unroll
    for (int d = 0; d < DD; d++) op[d] = acc[d] * inv;
}

// ---------------- Launch ----------------
extern "C" void kernel_launch(void* const* d_in, const int* in_sizes, int n_in,
                              void* d_out, int out_size) {
    const float* x        = (const float*)d_in[0];
    const int*   mask     = (const int*)d_in[1];     // bool marshalled as int32
    const float* qkv_w    = (const float*)d_in[2];
    const float* CP_U_w   = (const float*)d_in[3];
    const float* CP_U_b   = (const float*)d_in[4];
    const float* CP_V_w   = (const float*)d_in[5];
    const float* CP_V_b   = (const float*)d_in[6];
    const float* CP_C     = (const float*)d_in[7];
    const float* CP_att   = (const float*)d_in[8];
    const float* proj_w   = (const float*)d_in[9];
    const float* proj_b   = (const float*)d_in[10];
    float* outp = (float*)d_out;

    float *p_u, *p_u2, *p_qkv, *p_att, *p_Wbig, *p_Wp, *p_qkvwT, *p_projwT, *p_UwT, *p_bq, *p_bp;
    cudaGetSymbolAddress((void**)&p_u,     g_u);
    cudaGetSymbolAddress((void**)&p_u2,    g_u2);
    cudaGetSymbolAddress((void**)&p_qkv,   g_qkv);
    cudaGetSymbolAddress((void**)&p_att,   g_att);
    cudaGetSymbolAddress((void**)&p_Wbig,  g_Wbig);
    cudaGetSymbolAddress((void**)&p_Wp,    g_Wp);
    cudaGetSymbolAddress((void**)&p_qkvwT, g_qkvwT);
    cudaGetSymbolAddress((void**)&p_projwT,g_projwT);
    cudaGetSymbolAddress((void**)&p_UwT,   g_UwT);
    cudaGetSymbolAddress((void**)&p_bq,    g_bq);
    cudaGetSymbolAddress((void**)&p_bp,    g_bp);

    dim3 tdim(32, 8);
    // weight transposes: in[rows,cols] -> out[cols,rows]
    transpose_kernel<<<dim3(DIMC / 32, (3 * DIMC) / 32), tdim>>>(qkv_w, p_qkvwT, 3 * DIMC, DIMC);
    transpose_kernel<<<dim3(DIMC / 32, DIMC / 32), tdim>>>(proj_w, p_projwT, DIMC, DIMC);
    transpose_kernel<<<dim3(DIMC / 32, RR / 32), tdim>>>(CP_U_w, p_UwT, RR, DIMC);

    cpc_kernel<<<(RR * RR * 4) / 256, 256>>>(CP_C, CP_att);
    wfac_kernel<<<(RR * 2048) / 256, 256>>>(CP_V_w);
    bias_kernel<<<6, 256>>>(CP_V_b, proj_b);

    // u = x @ CP_U_w^T + CP_U_b          [8192,64]
    sgemm_dual<<<dim3(1, MTOT / 128), 256>>>(x, DIMC, p_UwT, DIMC,
                                             nullptr, 0, nullptr, 0,
                                             CP_U_b, p_u, MTOT, RR);
    // qkv = x@qkv_w^T + u@Wbig + bias    [8192,1536]
    sgemm_dual<<<dim3((3 * DIMC) / 128, MTOT / 128), 256>>>(x, DIMC, p_qkvwT, DIMC,
                                                            p_u, RR, p_Wbig, RR,
                                                            p_bq, p_qkv, MTOT, 3 * DIMC);
    // fused attention
    attn_kernel<<<dim3(NN / 128, HH, BB), 128>>>(p_qkv, mask, p_att);

    // u2 = att_out @ CP_U_w^T + CP_U_b
    sgemm_dual<<<dim3(1, MTOT / 128), 256>>>(p_att, DIMC, p_UwT, DIMC,
                                             nullptr, 0, nullptr, 0,
                                             CP_U_b, p_u2, MTOT, RR);
    // proj = att_out@proj_w^T + u2@Wp + (proj_b + S*CP_V_b)
    sgemm_dual<<<dim3(DIMC / 128, MTOT / 128), 256>>>(p_att, DIMC, p_projwT, DIMC,
                                                      p_u2, RR, p_Wp, RR,
                                                      p_bp, outp, MTOT, DIMC);
}

// round 4
// speedup vs baseline: 1.2126x; 1.2126x over previous
#include <cuda_runtime.h>
#include <cstdint>
#include <cstddef>

// ---------------- Problem constants ----------------
#define BB   8
#define NN   1024
#define DIMC 512
#define HH   8
#define DD   64
#define RR   64          // R1 = R2 = R = 64
#define MTOT (BB*NN)     // 8192
#define SCALE_ATT 0.125f // D^-0.5
#define S_CONST 1.0f

// ---------------- Scratch (__device__ globals; no allocation allowed) ----------------
__device__ float g_u    [MTOT*RR];
__device__ float g_u2   [MTOT*RR];
__device__ float g_qkv  [(size_t)MTOT*3*DIMC];
__device__ float g_att  [(size_t)MTOT*DIMC];
__device__ float g_CPc  [RR*RR*4];
__device__ float g_Wbig [RR*3*DIMC];
__device__ float g_Wp   [RR*DIMC];
__device__ float g_qkvwT[DIMC*3*DIMC];
__device__ float g_projwT[DIMC*DIMC];
__device__ float g_UwT  [DIMC*RR];
__device__ float g_bq   [3*DIMC];
__device__ float g_bp   [DIMC];

// ---------------- Small precompute kernels ----------------
__global__ void transpose_kernel(const float* __restrict__ in, float* __restrict__ out,
                                 int rows, int cols) {
    __shared__ float tile[32][33];
    int c0 = blockIdx.x * 32, r0 = blockIdx.y * 32;
    int tx = threadIdx.x, ty = threadIdx.y;
    #pragma unroll
    for (int i = 0; i < 32; i += 8) {
        int r = r0 + ty + i, c = c0 + tx;
        if (r < rows && c < cols) tile[ty + i][tx] = in[(size_t)r * cols + c];
    }
    __syncthreads();
    #pragma unroll
    for (int i = 0; i < 32; i += 8) {
        int c = c0 + ty + i, r = r0 + tx;
        if (r < rows && c < cols) out[(size_t)c * rows + r] = tile[tx][ty + i];
    }
}

__global__ void cpc_kernel(const float* __restrict__ CP_C, const float* __restrict__ CP_att) {
    int idx = blockIdx.x * 256 + threadIdx.x;
    if (idx >= RR * RR * 4) return;
    int f = idx & 3;
    int ij = idx >> 2;
    float s = 0.f;
    #pragma unroll 8
    for (int r = 0; r < RR; r++) s += CP_C[(ij << 6) + r] * CP_att[r * 4 + f];
    g_CPc[idx] = s;
}

__global__ void wfac_kernel(const float* __restrict__ CP_V_w) {
    int idx = blockIdx.x * 256 + threadIdx.x;
    int r = idx >> 11;
    int o = idx & 2047;
    int f, d;
    if (o < 3 * DIMC) { f = o >> 9; d = o & 511; }
    else              { f = 3;      d = o - 3 * DIMC; }
    float s = 0.f;
    #pragma unroll 8
    for (int ss = 0; ss < RR; ss++)
        s += g_CPc[((r << 6) + ss) * 4 + f] * CP_V_w[d * RR + ss];
    if (o < 3 * DIMC) g_Wbig[r * (3 * DIMC) + o] = s;
    else              g_Wp[r * DIMC + d] = s * S_CONST;
}

__global__ void bias_kernel(const float* __restrict__ CP_V_b, const float* __restrict__ proj_b) {
    int i = blockIdx.x * 256 + threadIdx.x;
    if (i < 3 * DIMC) g_bq[i] = CP_V_b[i & 511];
    if (i < DIMC)     g_bp[i] = proj_b[i] + S_CONST * CP_V_b[i];
}

// ---------------- tf32 helpers ----------------
__device__ __forceinline__ uint32_t f2tf(float x) {
    uint32_t r;
    asm("cvt.rna.tf32.f32 %0, %1;" : "=r"(r) : "f"(x));
    return r;
}

__device__ __forceinline__ void mma_tf32(float c[4], uint32_t a0, uint32_t a1,
                                         uint32_t a2, uint32_t a3,
                                         uint32_t b0, uint32_t b1) {
    asm volatile(
        "mma.sync.aligned.m16n8k8.row.col.f32.tf32.tf32.f32 "
        "{%0,%1,%2,%3}, {%4,%5,%6,%7}, {%8,%9}, {%0,%1,%2,%3};\n"
        : "+f"(c[0]), "+f"(c[1]), "+f"(c[2]), "+f"(c[3])
        : "r"(a0), "r"(a1), "r"(a2), "r"(a3), "r"(b0), "r"(b1));
}

// ---------------- Dual-source tf32 tensor-core GEMM ----------------
// C[M,N] = A1[M,K1]@B1[K1,N] + A2[M,K2]@B2[K2,N] + bias[N]
// A row-major (stride lda), B row-major [K,N]. BM=BN=128, BK=16, 256 thr (8 warps),
// warp tile 64x32 (2x4 warp grid), mma m16n8k8 tf32.
__global__ __launch_bounds__(256)
void gemm_tf32_dual(const float* __restrict__ A1, int lda1, const float* __restrict__ B1, int K1,
                    const float* __restrict__ A2, int lda2, const float* __restrict__ B2, int K2,
                    const float* __restrict__ bias, float* __restrict__ C,
                    int M, int N) {
    __shared__ uint32_t As[128][20];   // [m][k], pad 20 -> conflict-free frag reads
    __shared__ uint32_t Bs[128][20];   // [n][k] (transposed), pad 20

    int tid  = threadIdx.x;
    int lane = tid & 31;
    int warp = tid >> 5;
    int warp_m = (warp >> 2) * 64;     // 0, 64
    int warp_n = (warp & 3) * 32;      // 0,32,64,96
    int bm0 = blockIdx.y * 128;
    int bn0 = blockIdx.x * 128;
    int lr = lane >> 2;                // 0..7
    int lc = lane & 3;                 // 0..3

    float acc[4][4][4];
    #pragma unroll
    for (int i = 0; i < 4; i++)
        #pragma unroll
        for (int j = 0; j < 4; j++)
            #pragma unroll
            for (int k = 0; k < 4; k++) acc[i][j][k] = 0.f;

    int a_m = tid >> 2;                // 0..63
    int a_k = (tid & 3) * 4;           // 0,4,8,12
    int b_k = tid >> 4;                // 0..15
    int b_n = (tid & 15) * 8;          // 0..120

    #pragma unroll 1
    for (int pass = 0; pass < 2; pass++) {
        const float* A = pass ? A2 : A1;
        const float* B = pass ? B2 : B1;
        int K   = pass ? K2   : K1;
        int lda = pass ? lda2 : lda1;
        if (K == 0 || A == nullptr) continue;

        #pragma unroll 1
        for (int k0 = 0; k0 < K; k0 += 16) {
            float4 av0 = *(const float4*)&A[(size_t)(bm0 + a_m) * lda + k0 + a_k];
            float4 av1 = *(const float4*)&A[(size_t)(bm0 + a_m + 64) * lda + k0 + a_k];
            float4 bv0 = make_float4(0.f, 0.f, 0.f, 0.f);
            float4 bv1 = make_float4(0.f, 0.f, 0.f, 0.f);
            if (bn0 + b_n < N)
                bv0 = *(const float4*)&B[(size_t)(k0 + b_k) * N + bn0 + b_n];
            if (bn0 + b_n + 4 < N)
                bv1 = *(const float4*)&B[(size_t)(k0 + b_k) * N + bn0 + b_n + 4];
            __syncthreads();
            As[a_m][a_k + 0] = f2tf(av0.x);
            As[a_m][a_k + 1] = f2tf(av0.y);
            As[a_m][a_k + 2] = f2tf(av0.z);
            As[a_m][a_k + 3] = f2tf(av0.w);
            As[a_m + 64][a_k + 0] = f2tf(av1.x);
            As[a_m + 64][a_k + 1] = f2tf(av1.y);
            As[a_m + 64][a_k + 2] = f2tf(av1.z);
            As[a_m + 64][a_k + 3] = f2tf(av1.w);
            Bs[b_n + 0][b_k] = f2tf(bv0.x);
            Bs[b_n + 1][b_k] = f2tf(bv0.y);
            Bs[b_n + 2][b_k] = f2tf(bv0.z);
            Bs[b_n + 3][b_k] = f2tf(bv0.w);
            Bs[b_n + 4][b_k] = f2tf(bv1.x);
            Bs[b_n + 5][b_k] = f2tf(bv1.y);
            Bs[b_n + 6][b_k] = f2tf(bv1.z);
            Bs[b_n + 7][b_k] = f2tf(bv1.w);
            __syncthreads();

            #pragma unroll
            for (int kk = 0; kk < 16; kk += 8) {
                uint32_t af[4][4], bf[4][2];
                #pragma unroll
                for (int mt = 0; mt < 4; mt++) {
                    int r = warp_m + mt * 16 + lr;
                    af[mt][0] = As[r][kk + lc];
                    af[mt][1] = As[r + 8][kk + lc];
                    af[mt][2] = As[r][kk + 4 + lc];
                    af[mt][3] = As[r + 8][kk + 4 + lc];
                }
                #pragma unroll
                for (int nt = 0; nt < 4; nt++) {
                    int c = warp_n + nt * 8 + lr;
                    bf[nt][0] = Bs[c][kk + lc];
                    bf[nt][1] = Bs[c][kk + 4 + lc];
                }
                #pragma unroll
                for (int mt = 0; mt < 4; mt++)
                    #pragma unroll
                    for (int nt = 0; nt < 4; nt++)
                        mma_tf32(acc[mt][nt], af[mt][0], af[mt][1], af[mt][2], af[mt][3],
                                 bf[nt][0], bf[nt][1]);
            }
        }
    }

    // Epilogue: bias + store
    #pragma unroll
    for (int mt = 0; mt < 4; mt++) {
        int row = bm0 + warp_m + mt * 16 + lr;
        #pragma unroll
        for (int nt = 0; nt < 4; nt++) {
            int col = bn0 + warp_n + nt * 8 + lc * 2;
            if (col < N) {
                float2 v0 = make_float2(acc[mt][nt][0] + bias[col],
                                        acc[mt][nt][1] + bias[col + 1]);
                float2 v1 = make_float2(acc[mt][nt][2] + bias[col],
                                        acc[mt][nt][3] + bias[col + 1]);
                *(float2*)&C[(size_t)row * N + col] = v0;
                *(float2*)&C[(size_t)(row + 8) * N + col] = v1;
            }
        }
    }
}

// ---------------- Fused flash-style attention (fp32) ----------------
// grid: (N/128, H, B), block: 128 threads. Each thread owns one q row.
// mask is int32 (bool marshalled as int32 by the harness); nonzero = attend.
__global__ __launch_bounds__(128, 3)
void attn_kernel(const float* __restrict__ qkv, const int* __restrict__ mask,
                 float* __restrict__ out) {
    __shared__ float ks[64 * 64];
    __shared__ float vs[64 * 64];
    __shared__ int msk[64];
    int tid = threadIdx.x;
    int b = blockIdx.z, h = blockIdx.y;
    int row = blockIdx.x * 128 + tid;

    const float* qptr = qkv + ((size_t)(b * NN + row)) * (3 * DIMC) + h * DD;
    float q[DD];
    #pragma unroll
    for (int d = 0; d < DD; d++) q[d] = qptr[d] * SCALE_ATT;

    float m_run = -1e30f, l = 0.f;
    float acc[DD];
    #pragma unroll
    for (int d = 0; d < DD; d++) acc[d] = 0.f;

    #pragma unroll 1
    for (int t = 0; t < NN / 64; t++) {
        int m0 = t * 64;
        #pragma unroll
        for (int i = 0; i < 8; i++) {
            int idx = i * 128 + tid;
            int r = idx >> 4;
            int c = (idx & 15) << 2;
            size_t base = ((size_t)(b * NN + m0 + r)) * (3 * DIMC) + h * DD + c;
            *(float4*)&ks[r * 64 + c] = *(const float4*)&qkv[base + DIMC];
            *(float4*)&vs[r * 64 + c] = *(const float4*)&qkv[base + 2 * DIMC];
        }
        if (tid < 64) msk[tid] = mask[b * NN + m0 + tid];
        __syncthreads();

        #pragma unroll 1
        for (int m = 0; m < 64; m++) {
            if (!msk[m]) continue;
            const float4* kr = (const float4*)&ks[m * 64];
            float s = 0.f;
            #pragma unroll
            for (int dd = 0; dd < 16; dd++) {
                float4 kv = kr[dd];
                s += q[dd * 4 + 0] * kv.x + q[dd * 4 + 1] * kv.y
                   + q[dd * 4 + 2] * kv.z + q[dd * 4 + 3] * kv.w;
            }
            float p;
            if (s > m_run) {
                float sc = __expf(m_run - s);
                m_run = s;
                l *= sc;
                #pragma unroll
                for (int d = 0; d < DD; d++) acc[d] *= sc;
                p = 1.f;
            } else {
                p = __expf(s - m_run);
            }
            l += p;
            const float4* vr = (const float4*)&vs[m * 64];
            #pragma unroll
            for (int dd = 0; dd < 16; dd++) {
                float4 vv = vr[dd];
                acc[dd * 4 + 0] += p * vv.x;
                acc[dd * 4 + 1] += p * vv.y;
                acc[dd * 4 + 2] += p * vv.z;
                acc[dd * 4 + 3] += p * vv.w;
            }
        }
        __syncthreads();
    }

    float inv = 1.0f / l;
    float* op = out + ((size_t)(b * NN + row)) * DIMC + h * DD;
    #pragma unroll
    for (int d = 0; d < DD; d++) op[d] = acc[d] * inv;
}

// ---------------- Launch ----------------
extern "C" void kernel_launch(void* const* d_in, const int* in_sizes, int n_in,
                              void* d_out, int out_size) {
    const float* x        = (const float*)d_in[0];
    const int*   mask     = (const int*)d_in[1];     // bool marshalled as int32
    const float* qkv_w    = (const float*)d_in[2];
    const float* CP_U_w   = (const float*)d_in[3];
    const float* CP_U_b   = (const float*)d_in[4];
    const float* CP_V_w   = (const float*)d_in[5];
    const float* CP_V_b   = (const float*)d_in[6];
    const float* CP_C     = (const float*)d_in[7];
    const float* CP_att   = (const float*)d_in[8];
    const float* proj_w   = (const float*)d_in[9];
    const float* proj_b   = (const float*)d_in[10];
    float* outp = (float*)d_out;

    float *p_u, *p_u2, *p_qkv, *p_att, *p_Wbig, *p_Wp, *p_qkvwT, *p_projwT, *p_UwT, *p_bq, *p_bp;
    cudaGetSymbolAddress((void**)&p_u,     g_u);
    cudaGetSymbolAddress((void**)&p_u2,    g_u2);
    cudaGetSymbolAddress((void**)&p_qkv,   g_qkv);
    cudaGetSymbolAddress((void**)&p_att,   g_att);
    cudaGetSymbolAddress((void**)&p_Wbig,  g_Wbig);
    cudaGetSymbolAddress((void**)&p_Wp,    g_Wp);
    cudaGetSymbolAddress((void**)&p_qkvwT, g_qkvwT);
    cudaGetSymbolAddress((void**)&p_projwT,g_projwT);
    cudaGetSymbolAddress((void**)&p_UwT,   g_UwT);
    cudaGetSymbolAddress((void**)&p_bq,    g_bq);
    cudaGetSymbolAddress((void**)&p_bp,    g_bp);

    dim3 tdim(32, 8);
    transpose_kernel<<<dim3(DIMC / 32, (3 * DIMC) / 32), tdim>>>(qkv_w, p_qkvwT, 3 * DIMC, DIMC);
    transpose_kernel<<<dim3(DIMC / 32, DIMC / 32), tdim>>>(proj_w, p_projwT, DIMC, DIMC);
    transpose_kernel<<<dim3(DIMC / 32, RR / 32), tdim>>>(CP_U_w, p_UwT, RR, DIMC);

    cpc_kernel<<<(RR * RR * 4) / 256, 256>>>(CP_C, CP_att);
    wfac_kernel<<<(RR * 2048) / 256, 256>>>(CP_V_w);
    bias_kernel<<<6, 256>>>(CP_V_b, proj_b);

    // u = x @ CP_U_w^T + CP_U_b          [8192,64]
    gemm_tf32_dual<<<dim3(1, MTOT / 128), 256>>>(x, DIMC, p_UwT, DIMC,
                                                 nullptr, 0, nullptr, 0,
                                                 CP_U_b, p_u, MTOT, RR);
    // qkv = x@qkv_w^T + u@Wbig + bias    [8192,1536]
    gemm_tf32_dual<<<dim3((3 * DIMC) / 128, MTOT / 128), 256>>>(x, DIMC, p_qkvwT, DIMC,
                                                                p_u, RR, p_Wbig, RR,
                                                                p_bq, p_qkv, MTOT, 3 * DIMC);
    // fused attention
    attn_kernel<<<dim3(NN / 128, HH, BB), 128>>>(p_qkv, mask, p_att);

    // u2 = att_out @ CP_U_w^T + CP_U_b
    gemm_tf32_dual<<<dim3(1, MTOT / 128), 256>>>(p_att, DIMC, p_UwT, DIMC,
                                                 nullptr, 0, nullptr, 0,
                                                 CP_U_b, p_u2, MTOT, RR);
    // proj = att_out@proj_w^T + u2@Wp + (proj_b + S*CP_V_b)
    gemm_tf32_dual<<<dim3(DIMC / 128, MTOT / 128), 256>>>(p_att, DIMC, p_projwT, DIMC,
                                                          p_u2, RR, p_Wp, RR,
                                                          p_bp, outp, MTOT, DIMC);
}

// round 6
// speedup vs baseline: 2.2208x; 1.8314x over previous
#include <cuda_runtime.h>
#include <cstdint>
#include <cstddef>

// ---------------- Problem constants ----------------
#define BB   8
#define NN   1024
#define DIMC 512
#define HH   8
#define DD   64
#define RR   64          // R1 = R2 = R = 64
#define MTOT (BB*NN)     // 8192
#define SCALE_ATT 0.125f // D^-0.5
#define S_CONST 1.0f

// ---------------- Scratch (__device__ globals; no allocation allowed) ----------------
__device__ float g_u    [MTOT*RR];
__device__ float g_u2   [MTOT*RR];
__device__ float g_qkv  [(size_t)MTOT*3*DIMC];
__device__ float g_att  [(size_t)MTOT*DIMC];
__device__ float g_CPc  [RR*RR*4];
__device__ float g_Wbig [RR*3*DIMC];
__device__ float g_Wp   [RR*DIMC];
__device__ float g_qkvwT[DIMC*3*DIMC];
__device__ float g_projwT[DIMC*DIMC];
__device__ float g_UwT  [DIMC*RR];
__device__ float g_bq   [3*DIMC];
__device__ float g_bp   [DIMC];

// ---------------- Small precompute kernels ----------------
__global__ void transpose_kernel(const float* __restrict__ in, float* __restrict__ out,
                                 int rows, int cols) {
    __shared__ float tile[32][33];
    int c0 = blockIdx.x * 32, r0 = blockIdx.y * 32;
    int tx = threadIdx.x, ty = threadIdx.y;
    #pragma unroll
    for (int i = 0; i < 32; i += 8) {
        int r = r0 + ty + i, c = c0 + tx;
        if (r < rows && c < cols) tile[ty + i][tx] = in[(size_t)r * cols + c];
    }
    __syncthreads();
    #pragma unroll
    for (int i = 0; i < 32; i += 8) {
        int c = c0 + ty + i, r = r0 + tx;
        if (r < rows && c < cols) out[(size_t)c * rows + r] = tile[tx][ty + i];
    }
}

__global__ void cpc_kernel(const float* __restrict__ CP_C, const float* __restrict__ CP_att) {
    int idx = blockIdx.x * 256 + threadIdx.x;
    if (idx >= RR * RR * 4) return;
    int f = idx & 3;
    int ij = idx >> 2;
    float s = 0.f;
    #pragma unroll 8
    for (int r = 0; r < RR; r++) s += CP_C[(ij << 6) + r] * CP_att[r * 4 + f];
    g_CPc[idx] = s;
}

__global__ void wfac_kernel(const float* __restrict__ CP_V_w) {
    int idx = blockIdx.x * 256 + threadIdx.x;
    int r = idx >> 11;
    int o = idx & 2047;
    int f, d;
    if (o < 3 * DIMC) { f = o >> 9; d = o & 511; }
    else              { f = 3;      d = o - 3 * DIMC; }
    float s = 0.f;
    #pragma unroll 8
    for (int ss = 0; ss < RR; ss++)
        s += g_CPc[((r << 6) + ss) * 4 + f] * CP_V_w[d * RR + ss];
    if (o < 3 * DIMC) g_Wbig[r * (3 * DIMC) + o] = s;
    else              g_Wp[r * DIMC + d] = s * S_CONST;
}

__global__ void bias_kernel(const float* __restrict__ CP_V_b, const float* __restrict__ proj_b) {
    int i = blockIdx.x * 256 + threadIdx.x;
    if (i < 3 * DIMC) g_bq[i] = CP_V_b[i & 511];
    if (i < DIMC)     g_bp[i] = proj_b[i] + S_CONST * CP_V_b[i];
}

// ---------------- tf32 helpers ----------------
__device__ __forceinline__ uint32_t f2tf(float x) {
    uint32_t r;
    asm("cvt.rna.tf32.f32 %0, %1;" : "=r"(r) : "f"(x));
    return r;
}

__device__ __forceinline__ void mma_tf32(float c[4], uint32_t a0, uint32_t a1,
                                         uint32_t a2, uint32_t a3,
                                         uint32_t b0, uint32_t b1) {
    asm volatile(
        "mma.sync.aligned.m16n8k8.row.col.f32.tf32.tf32.f32 "
        "{%0,%1,%2,%3}, {%4,%5,%6,%7}, {%8,%9}, {%0,%1,%2,%3};\n"
        : "+f"(c[0]), "+f"(c[1]), "+f"(c[2]), "+f"(c[3])
        : "r"(a0), "r"(a1), "r"(a2), "r"(a3), "r"(b0), "r"(b1));
}

// ---------------- Dual-source tf32 tensor-core GEMM ----------------
__global__ __launch_bounds__(256)
void gemm_tf32_dual(const float* __restrict__ A1, int lda1, const float* __restrict__ B1, int K1,
                    const float* __restrict__ A2, int lda2, const float* __restrict__ B2, int K2,
                    const float* __restrict__ bias, float* __restrict__ C,
                    int M, int N) {
    __shared__ uint32_t As[128][20];
    __shared__ uint32_t Bs[128][20];

    int tid  = threadIdx.x;
    int lane = tid & 31;
    int warp = tid >> 5;
    int warp_m = (warp >> 2) * 64;
    int warp_n = (warp & 3) * 32;
    int bm0 = blockIdx.y * 128;
    int bn0 = blockIdx.x * 128;
    int lr = lane >> 2;
    int lc = lane & 3;

    float acc[4][4][4];
    #pragma unroll
    for (int i = 0; i < 4; i++)
        #pragma unroll
        for (int j = 0; j < 4; j++)
            #pragma unroll
            for (int k = 0; k < 4; k++) acc[i][j][k] = 0.f;

    int a_m = tid >> 2;
    int a_k = (tid & 3) * 4;
    int b_k = tid >> 4;
    int b_n = (tid & 15) * 8;

    #pragma unroll 1
    for (int pass = 0; pass < 2; pass++) {
        const float* A = pass ? A2 : A1;
        const float* B = pass ? B2 : B1;
        int K   = pass ? K2   : K1;
        int lda = pass ? lda2 : lda1;
        if (K == 0 || A == nullptr) continue;

        #pragma unroll 1
        for (int k0 = 0; k0 < K; k0 += 16) {
            float4 av0 = *(const float4*)&A[(size_t)(bm0 + a_m) * lda + k0 + a_k];
            float4 av1 = *(const float4*)&A[(size_t)(bm0 + a_m + 64) * lda + k0 + a_k];
            float4 bv0 = make_float4(0.f, 0.f, 0.f, 0.f);
            float4 bv1 = make_float4(0.f, 0.f, 0.f, 0.f);
            if (bn0 + b_n < N)
                bv0 = *(const float4*)&B[(size_t)(k0 + b_k) * N + bn0 + b_n];
            if (bn0 + b_n + 4 < N)
                bv1 = *(const float4*)&B[(size_t)(k0 + b_k) * N + bn0 + b_n + 4];
            __syncthreads();
            As[a_m][a_k + 0] = f2tf(av0.x);
            As[a_m][a_k + 1] = f2tf(av0.y);
            As[a_m][a_k + 2] = f2tf(av0.z);
            As[a_m][a_k + 3] = f2tf(av0.w);
            As[a_m + 64][a_k + 0] = f2tf(av1.x);
            As[a_m + 64][a_k + 1] = f2tf(av1.y);
            As[a_m + 64][a_k + 2] = f2tf(av1.z);
            As[a_m + 64][a_k + 3] = f2tf(av1.w);
            Bs[b_n + 0][b_k] = f2tf(bv0.x);
            Bs[b_n + 1][b_k] = f2tf(bv0.y);
            Bs[b_n + 2][b_k] = f2tf(bv0.z);
            Bs[b_n + 3][b_k] = f2tf(bv0.w);
            Bs[b_n + 4][b_k] = f2tf(bv1.x);
            Bs[b_n + 5][b_k] = f2tf(bv1.y);
            Bs[b_n + 6][b_k] = f2tf(bv1.z);
            Bs[b_n + 7][b_k] = f2tf(bv1.w);
            __syncthreads();

            #pragma unroll
            for (int kk = 0; kk < 16; kk += 8) {
                uint32_t af[4][4], bf[4][2];
                #pragma unroll
                for (int mt = 0; mt < 4; mt++) {
                    int r = warp_m + mt * 16 + lr;
                    af[mt][0] = As[r][kk + lc];
                    af[mt][1] = As[r + 8][kk + lc];
                    af[mt][2] = As[r][kk + 4 + lc];
                    af[mt][3] = As[r + 8][kk + 4 + lc];
                }
                #pragma unroll
                for (int nt = 0; nt < 4; nt++) {
                    int c = warp_n + nt * 8 + lr;
                    bf[nt][0] = Bs[c][kk + lc];
                    bf[nt][1] = Bs[c][kk + 4 + lc];
                }
                #pragma unroll
                for (int mt = 0; mt < 4; mt++)
                    #pragma unroll
                    for (int nt = 0; nt < 4; nt++)
                        mma_tf32(acc[mt][nt], af[mt][0], af[mt][1], af[mt][2], af[mt][3],
                                 bf[nt][0], bf[nt][1]);
            }
        }
    }

    #pragma unroll
    for (int mt = 0; mt < 4; mt++) {
        int row = bm0 + warp_m + mt * 16 + lr;
        #pragma unroll
        for (int nt = 0; nt < 4; nt++) {
            int col = bn0 + warp_n + nt * 8 + lc * 2;
            if (col < N) {
                float2 v0 = make_float2(acc[mt][nt][0] + bias[col],
                                        acc[mt][nt][1] + bias[col + 1]);
                float2 v1 = make_float2(acc[mt][nt][2] + bias[col],
                                        acc[mt][nt][3] + bias[col + 1]);
                *(float2*)&C[(size_t)row * N + col] = v0;
                *(float2*)&C[(size_t)(row + 8) * N + col] = v1;
            }
        }
    }
}

// ---------------- Tensor-core flash attention (tf32 mma, fp32 softmax) ----------------
// grid (N/128, H, B), 256 threads (8 warps). Warp w owns q rows [w*16, w*16+16).
// smem (floats): SP[128][68] (Q staging, then S/P), Ks[64][68], Vs[64][72],
//                maskadd[64], facs[128]
#define SP_STRIDE 68
#define KS_STRIDE 68
#define VS_STRIDE 72
#define ATT_SP_OFF   0
#define ATT_KS_OFF   (128*SP_STRIDE)
#define ATT_VS_OFF   (ATT_KS_OFF + 64*KS_STRIDE)
#define ATT_MA_OFF   (ATT_VS_OFF + 64*VS_STRIDE)
#define ATT_FAC_OFF  (ATT_MA_OFF + 64)
#define ATT_SMEM_FLOATS (ATT_FAC_OFF + 128)
#define ATT_SMEM_BYTES  (ATT_SMEM_FLOATS * 4)

extern __shared__ float att_sm[];

__global__ __launch_bounds__(256, 2)
void attn_mma_kernel(const float* __restrict__ qkv, const int* __restrict__ mask,
                     float* __restrict__ out) {
    float*    SP   = att_sm + ATT_SP_OFF;
    float*    Ks   = att_sm + ATT_KS_OFF;
    float*    Vs   = att_sm + ATT_VS_OFF;
    float*    ma   = att_sm + ATT_MA_OFF;
    float*    facs = att_sm + ATT_FAC_OFF;
    uint32_t* SPu  = (uint32_t*)SP;
    uint32_t* Ksu  = (uint32_t*)Ks;
    uint32_t* Vsu  = (uint32_t*)Vs;

    int tid = threadIdx.x, lane = tid & 31, warp = tid >> 5;
    int b = blockIdx.z, h = blockIdx.y;
    int brow = blockIdx.x * 128;
    int g = lane >> 2, tg = lane & 3;
    int wr = warp * 16;
    int row_l = lane >> 1, half = lane & 1;

    // --- stage Q (x SCALE, tf32) into SP ---
    {
        int row = tid >> 1, hf = tid & 1;
        const float* qp = qkv + ((size_t)(b * NN + brow + row)) * (3 * DIMC) + h * DD + hf * 32;
        uint32_t* dst = SPu + row * SP_STRIDE + hf * 32;
        #pragma unroll
        for (int i = 0; i < 8; i++) {
            float4 v = *(const float4*)(qp + i * 4);
            dst[i * 4 + 0] = f2tf(v.x * SCALE_ATT);
            dst[i * 4 + 1] = f2tf(v.y * SCALE_ATT);
            dst[i * 4 + 2] = f2tf(v.z * SCALE_ATT);
            dst[i * 4 + 3] = f2tf(v.w * SCALE_ATT);
        }
    }
    __syncthreads();

    // --- Q fragments, register-resident for whole kernel ---
    uint32_t aq[8][4];
    #pragma unroll
    for (int kk = 0; kk < 8; kk++) {
        aq[kk][0] = SPu[(wr + g) * SP_STRIDE + kk * 8 + tg];
        aq[kk][1] = SPu[(wr + g + 8) * SP_STRIDE + kk * 8 + tg];
        aq[kk][2] = SPu[(wr + g) * SP_STRIDE + kk * 8 + 4 + tg];
        aq[kk][3] = SPu[(wr + g + 8) * SP_STRIDE + kk * 8 + 4 + tg];
    }

    float o[8][4];
    #pragma unroll
    for (int nt = 0; nt < 8; nt++)
        #pragma unroll
        for (int i = 0; i < 4; i++) o[nt][i] = 0.f;
    float m_run = -1e30f, l_run = 0.f;

    #pragma unroll 1
    for (int t = 0; t < NN / 64; t++) {
        int k0 = t * 64;
        __syncthreads();   // prev iter done with Ks/Vs
        // coop load K,V tiles (tf32), and mask->additive
        {
            int r = tid >> 2, c4 = (tid & 3) * 16;
            size_t base = ((size_t)(b * NN + k0 + r)) * (3 * DIMC) + h * DD + c4;
            const float* kp = qkv + base + DIMC;
            const float* vp = qkv + base + 2 * DIMC;
            uint32_t* kd = Ksu + r * KS_STRIDE + c4;
            uint32_t* vd = Vsu + r * VS_STRIDE + c4;
            #pragma unroll
            for (int i = 0; i < 4; i++) {
                float4 kv = *(const float4*)(kp + i * 4);
                float4 vv = *(const float4*)(vp + i * 4);
                kd[i * 4 + 0] = f2tf(kv.x);
                kd[i * 4 + 1] = f2tf(kv.y);
                kd[i * 4 + 2] = f2tf(kv.z);
                kd[i * 4 + 3] = f2tf(kv.w);
                vd[i * 4 + 0] = f2tf(vv.x);
                vd[i * 4 + 1] = f2tf(vv.y);
                vd[i * 4 + 2] = f2tf(vv.z);
                vd[i * 4 + 3] = f2tf(vv.w);
            }
            if (tid < 64) ma[tid] = mask[b * NN + k0 + tid] ? 0.f : -1e30f;
        }
        __syncthreads();

        // QK^T: S[16 x 64] per warp
        float s[8][4];
        #pragma unroll
        for (int nt = 0; nt < 8; nt++)
            #pragma unroll
            for (int i = 0; i < 4; i++) s[nt][i] = 0.f;
        #pragma unroll
        for (int kk = 0; kk < 8; kk++) {
            #pragma unroll
            for (int nt = 0; nt < 8; nt++) {
                uint32_t b0 = Ksu[(nt * 8 + g) * KS_STRIDE + kk * 8 + tg];
                uint32_t b1 = Ksu[(nt * 8 + g) * KS_STRIDE + kk * 8 + 4 + tg];
                mma_tf32(s[nt], aq[kk][0], aq[kk][1], aq[kk][2], aq[kk][3], b0, b1);
            }
        }
        // write S fragments to SP (warp-private rows)
        #pragma unroll
        for (int nt = 0; nt < 8; nt++) {
            *(float2*)&SP[(wr + g) * SP_STRIDE + nt * 8 + 2 * tg]     = make_float2(s[nt][0], s[nt][1]);
            *(float2*)&SP[(wr + g + 8) * SP_STRIDE + nt * 8 + 2 * tg] = make_float2(s[nt][2], s[nt][3]);
        }
        __syncwarp();

        // online softmax: lane pair per row; lane handles 32 cols
        {
            float* srow = SP + (wr + row_l) * SP_STRIDE + half * 32;
            const float* mrow = ma + half * 32;
            float tm = -1e30f;
            #pragma unroll
            for (int j = 0; j < 32; j++) tm = fmaxf(tm, srow[j] + mrow[j]);
            tm = fmaxf(tm, __shfl_xor_sync(0xffffffffu, tm, 1));
            float m_new = fmaxf(m_run, tm);
            float fac = __expf(m_run - m_new);
            float ps = 0.f;
            uint32_t* prow = SPu + (wr + row_l) * SP_STRIDE + half * 32;
            #pragma unroll
            for (int j = 0; j < 32; j++) {
                float p = __expf(srow[j] + mrow[j] - m_new);
                ps += p;
                prow[j] = f2tf(p);
            }
            ps += __shfl_xor_sync(0xffffffffu, ps, 1);
            l_run = l_run * fac + ps;
            m_run = m_new;
            if (half == 0) facs[wr + row_l] = fac;
        }
        __syncwarp();

        // rescale O, then O += P @ V
        float fg  = facs[wr + g];
        float fg8 = facs[wr + g + 8];
        #pragma unroll
        for (int nt = 0; nt < 8; nt++) {
            o[nt][0] *= fg;  o[nt][1] *= fg;
            o[nt][2] *= fg8; o[nt][3] *= fg8;
        }
        #pragma unroll
        for (int kk = 0; kk < 8; kk++) {
            uint32_t a0 = SPu[(wr + g) * SP_STRIDE + kk * 8 + tg];
            uint32_t a1 = SPu[(wr + g + 8) * SP_STRIDE + kk * 8 + tg];
            uint32_t a2 = SPu[(wr + g) * SP_STRIDE + kk * 8 + 4 + tg];
            uint32_t a3 = SPu[(wr + g + 8) * SP_STRIDE + kk * 8 + 4 + tg];
            #pragma unroll
            for (int nt = 0; nt < 8; nt++) {
                uint32_t b0 = Vsu[(kk * 8 + tg) * VS_STRIDE + nt * 8 + g];
                uint32_t b1 = Vsu[(kk * 8 + tg + 4) * VS_STRIDE + nt * 8 + g];
                mma_tf32(o[nt], a0, a1, a2, a3, b0, b1);
            }
        }
    }

    // epilogue: divide by l, store
    if (half == 0) facs[wr + row_l] = l_run;
    __syncwarp();
    float il  = 1.0f / facs[wr + g];
    float il8 = 1.0f / facs[wr + g + 8];
    size_t r0 = ((size_t)(b * NN + brow + wr + g)) * DIMC + h * DD;
    size_t r8 = ((size_t)(b * NN + brow + wr + g + 8)) * DIMC + h * DD;
    #pragma unroll
    for (int nt = 0; nt < 8; nt++) {
        int col = nt * 8 + 2 * tg;
        *(float2*)&out[r0 + col] = make_float2(o[nt][0] * il,  o[nt][1] * il);
        *(float2*)&out[r8 + col] = make_float2(o[nt][2] * il8, o[nt][3] * il8);
    }
}

// ---------------- Launch ----------------
extern "C" void kernel_launch(void* const* d_in, const int* in_sizes, int n_in,
                              void* d_out, int out_size) {
    const float* x        = (const float*)d_in[0];
    const int*   mask     = (const int*)d_in[1];     // bool marshalled as int32
    const float* qkv_w    = (const float*)d_in[2];
    const float* CP_U_w   = (const float*)d_in[3];
    const float* CP_U_b   = (const float*)d_in[4];
    const float* CP_V_w   = (const float*)d_in[5];
    const float* CP_V_b   = (const float*)d_in[6];
    const float* CP_C     = (const float*)d_in[7];
    const float* CP_att   = (const float*)d_in[8];
    const float* proj_w   = (const float*)d_in[9];
    const float* proj_b   = (const float*)d_in[10];
    float* outp = (float*)d_out;

    float *p_u, *p_u2, *p_qkv, *p_att, *p_Wbig, *p_Wp, *p_qkvwT, *p_projwT, *p_UwT, *p_bq, *p_bp;
    cudaGetSymbolAddress((void**)&p_u,     g_u);
    cudaGetSymbolAddress((void**)&p_u2,    g_u2);
    cudaGetSymbolAddress((void**)&p_qkv,   g_qkv);
    cudaGetSymbolAddress((void**)&p_att,   g_att);
    cudaGetSymbolAddress((void**)&p_Wbig,  g_Wbig);
    cudaGetSymbolAddress((void**)&p_Wp,    g_Wp);
    cudaGetSymbolAddress((void**)&p_qkvwT, g_qkvwT);
    cudaGetSymbolAddress((void**)&p_projwT,g_projwT);
    cudaGetSymbolAddress((void**)&p_UwT,   g_UwT);
    cudaGetSymbolAddress((void**)&p_bq,    g_bq);
    cudaGetSymbolAddress((void**)&p_bp,    g_bp);

    static bool attr_set = false;
    if (!attr_set) {
        cudaFuncSetAttribute(attn_mma_kernel,
                             cudaFuncAttributeMaxDynamicSharedMemorySize, ATT_SMEM_BYTES);
        attr_set = true;
    }

    dim3 tdim(32, 8);
    transpose_kernel<<<dim3(DIMC / 32, (3 * DIMC) / 32), tdim>>>(qkv_w, p_qkvwT, 3 * DIMC, DIMC);
    transpose_kernel<<<dim3(DIMC / 32, DIMC / 32), tdim>>>(proj_w, p_projwT, DIMC, DIMC);
    transpose_kernel<<<dim3(DIMC / 32, RR / 32), tdim>>>(CP_U_w, p_UwT, RR, DIMC);

    cpc_kernel<<<(RR * RR * 4) / 256, 256>>>(CP_C, CP_att);
    wfac_kernel<<<(RR * 2048) / 256, 256>>>(CP_V_w);
    bias_kernel<<<6, 256>>>(CP_V_b, proj_b);

    // u = x @ CP_U_w^T + CP_U_b          [8192,64]
    gemm_tf32_dual<<<dim3(1, MTOT / 128), 256>>>(x, DIMC, p_UwT, DIMC,
                                                 nullptr, 0, nullptr, 0,
                                                 CP_U_b, p_u, MTOT, RR);
    // qkv = x@qkv_w^T + u@Wbig + bias    [8192,1536]
    gemm_tf32_dual<<<dim3((3 * DIMC) / 128, MTOT / 128), 256>>>(x, DIMC, p_qkvwT, DIMC,
                                                                p_u, RR, p_Wbig, RR,
                                                                p_bq, p_qkv, MTOT, 3 * DIMC);
    // tensor-core flash attention
    attn_mma_kernel<<<dim3(NN / 128, HH, BB), 256, ATT_SMEM_BYTES>>>(p_qkv, mask, p_att);

    // u2 = att_out @ CP_U_w^T + CP_U_b
    gemm_tf32_dual<<<dim3(1, MTOT / 128), 256>>>(p_att, DIMC, p_UwT, DIMC,
                                                 nullptr, 0, nullptr, 0,
                                                 CP_U_b, p_u2, MTOT, RR);
    // proj = att_out@proj_w^T + u2@Wp + (proj_b + S*CP_V_b)
    gemm_tf32_dual<<<dim3(DIMC / 128, MTOT / 128), 256>>>(p_att, DIMC, p_projwT, DIMC,
                                                          p_u2, RR, p_Wp, RR,
                                                          p_bp, outp, MTOT, DIMC);
}

// round 7
// speedup vs baseline: 2.5782x; 1.1609x over previous
#include <cuda_runtime.h>
#include <cstdint>
#include <cstddef>

// ---------------- Problem constants ----------------
#define BB   8
#define NN   1024
#define DIMC 512
#define HH   8
#define DD   64
#define RR   64          // R1 = R2 = R = 64
#define MTOT (BB*NN)     // 8192
#define SCALE_ATT 0.125f // D^-0.5
#define S_CONST 1.0f

// ---------------- Scratch (__device__ globals; no allocation allowed) ----------------
__device__ float g_qkv  [(size_t)MTOT*3*DIMC];
__device__ float g_att  [(size_t)MTOT*DIMC];
__device__ float g_CPc  [RR*RR*4];
__device__ float g_Wbig [RR*3*DIMC];        // [r, o] o in [0,1536): q|k|v factors
__device__ float g_Wp   [RR*DIMC];          // proj factor (pre-scaled by S)
__device__ float g_qkvwT[DIMC*3*DIMC];      // qkv_w^T  [512,1536]
__device__ float g_projwT[DIMC*DIMC];       // proj_w^T [512,512]
__device__ float g_UwT  [DIMC*RR];          // CP_U_w^T [512,64]
__device__ float g_Wcq  [(size_t)DIMC*3*DIMC]; // qkv_wT + UwT@Wbig
__device__ float g_Wcp  [DIMC*DIMC];           // projwT + UwT@Wp
__device__ float g_bq   [3*DIMC];           // CP_V_b tiled x3
__device__ float g_bp   [DIMC];             // proj_b + S*CP_V_b
__device__ float g_bqc  [3*DIMC];           // g_bq + CP_U_b@Wbig
__device__ float g_bpc  [DIMC];             // g_bp + CP_U_b@Wp

// ---------------- Small precompute kernels ----------------
__global__ void transpose_kernel(const float* __restrict__ in, float* __restrict__ out,
                                 int rows, int cols) {
    __shared__ float tile[32][33];
    int c0 = blockIdx.x * 32, r0 = blockIdx.y * 32;
    int tx = threadIdx.x, ty = threadIdx.y;
    #pragma unroll
    for (int i = 0; i < 32; i += 8) {
        int r = r0 + ty + i, c = c0 + tx;
        if (r < rows && c < cols) tile[ty + i][tx] = in[(size_t)r * cols + c];
    }
    __syncthreads();
    #pragma unroll
    for (int i = 0; i < 32; i += 8) {
        int c = c0 + ty + i, r = r0 + tx;
        if (r < rows && c < cols) out[(size_t)c * rows + r] = tile[tx][ty + i];
    }
}

__global__ void cpc_kernel(const float* __restrict__ CP_C, const float* __restrict__ CP_att) {
    int idx = blockIdx.x * 256 + threadIdx.x;
    if (idx >= RR * RR * 4) return;
    int f = idx & 3;
    int ij = idx >> 2;
    float s = 0.f;
    #pragma unroll 8
    for (int r = 0; r < RR; r++) s += CP_C[(ij << 6) + r] * CP_att[r * 4 + f];
    g_CPc[idx] = s;
}

__global__ void wfac_kernel(const float* __restrict__ CP_V_w) {
    int idx = blockIdx.x * 256 + threadIdx.x;
    int r = idx >> 11;
    int o = idx & 2047;
    int f, d;
    if (o < 3 * DIMC) { f = o >> 9; d = o & 511; }
    else              { f = 3;      d = o - 3 * DIMC; }
    float s = 0.f;
    #pragma unroll 8
    for (int ss = 0; ss < RR; ss++)
        s += g_CPc[((r << 6) + ss) * 4 + f] * CP_V_w[d * RR + ss];
    if (o < 3 * DIMC) g_Wbig[r * (3 * DIMC) + o] = s;
    else              g_Wp[r * DIMC + d] = s * S_CONST;
}

__global__ void bias_kernel(const float* __restrict__ CP_V_b, const float* __restrict__ proj_b) {
    int i = blockIdx.x * 256 + threadIdx.x;
    if (i < 3 * DIMC) g_bq[i] = CP_V_b[i & 511];
    if (i < DIMC)     g_bp[i] = proj_b[i] + S_CONST * CP_V_b[i];
}

// bias folds: bqc = bq + CP_U_b@Wbig ; bpc = bp + CP_U_b@Wp
__global__ void biascomb_kernel(const float* __restrict__ CP_U_b) {
    int i = blockIdx.x * 256 + threadIdx.x;   // 2048 total
    if (i < 3 * DIMC) {
        float s = g_bq[i];
        #pragma unroll 8
        for (int r = 0; r < RR; r++) s += CP_U_b[r] * g_Wbig[r * (3 * DIMC) + i];
        g_bqc[i] = s;
    } else if (i < 3 * DIMC + DIMC) {
        int d = i - 3 * DIMC;
        float s = g_bp[d];
        #pragma unroll 8
        for (int r = 0; r < RR; r++) s += CP_U_b[r] * g_Wp[r * DIMC + d];
        g_bpc[d] = s;
    }
}

// ---------------- tf32 helpers ----------------
__device__ __forceinline__ uint32_t f2tf(float x) {
    uint32_t r;
    asm("cvt.rna.tf32.f32 %0, %1;" : "=r"(r) : "f"(x));
    return r;
}

__device__ __forceinline__ void mma_tf32(float c[4], uint32_t a0, uint32_t a1,
                                         uint32_t a2, uint32_t a3,
                                         uint32_t b0, uint32_t b1) {
    asm volatile(
        "mma.sync.aligned.m16n8k8.row.col.f32.tf32.tf32.f32 "
        "{%0,%1,%2,%3}, {%4,%5,%6,%7}, {%8,%9}, {%0,%1,%2,%3};\n"
        : "+f"(c[0]), "+f"(c[1]), "+f"(c[2]), "+f"(c[3])
        : "r"(a0), "r"(a1), "r"(a2), "r"(a3), "r"(b0), "r"(b1));
}

// ---------------- Single-source pipelined tf32 GEMM ----------------
// C[M,N] = A[M,K]@B[K,N] (+ bias[N]) (+ Cadd[M,N])
// M,N multiples of 128; K multiple of 16. A stride lda, B row length N.
// BM=BN=128, BK=16, 256 thr (8 warps), warp tile 64x32, mma m16n8k8 tf32.
// Register-prefetch software pipeline hides LDG under the mma stage.
__global__ __launch_bounds__(256)
void gemm_tf32(const float* __restrict__ A, int lda,
               const float* __restrict__ B, int K,
               const float* __restrict__ bias, const float* __restrict__ Cadd,
               float* __restrict__ C, int N) {
    __shared__ uint32_t As[128][20];
    __shared__ uint32_t Bs[128][20];

    int tid  = threadIdx.x;
    int lane = tid & 31;
    int warp = tid >> 5;
    int warp_m = (warp >> 2) * 64;
    int warp_n = (warp & 3) * 32;
    int bm0 = blockIdx.y * 128;
    int bn0 = blockIdx.x * 128;
    int lr = lane >> 2;
    int lc = lane & 3;

    float acc[4][4][4];
    #pragma unroll
    for (int i = 0; i < 4; i++)
        #pragma unroll
        for (int j = 0; j < 4; j++)
            #pragma unroll
            for (int k = 0; k < 4; k++) acc[i][j][k] = 0.f;

    int a_m = tid >> 2;                // 0..63
    int a_k = (tid & 3) * 4;           // 0,4,8,12
    int b_k = tid >> 4;                // 0..15
    int b_n = (tid & 15) * 8;          // 0..120

    const float* pa0 = &A[(size_t)(bm0 + a_m) * lda + a_k];
    const float* pa1 = &A[(size_t)(bm0 + a_m + 64) * lda + a_k];
    const float* pb  = &B[(size_t)b_k * N + bn0 + b_n];

    // prefetch tile 0
    float4 av0 = *(const float4*)pa0;
    float4 av1 = *(const float4*)pa1;
    float4 bv0 = *(const float4*)pb;
    float4 bv1 = *(const float4*)(pb + 4);

    #pragma unroll 1
    for (int k0 = 0; k0 < K; k0 += 16) {
        __syncthreads();               // previous mma done with smem
        As[a_m][a_k + 0] = f2tf(av0.x);
        As[a_m][a_k + 1] = f2tf(av0.y);
        As[a_m][a_k + 2] = f2tf(av0.z);
        As[a_m][a_k + 3] = f2tf(av0.w);
        As[a_m + 64][a_k + 0] = f2tf(av1.x);
        As[a_m + 64][a_k + 1] = f2tf(av1.y);
        As[a_m + 64][a_k + 2] = f2tf(av1.z);
        As[a_m + 64][a_k + 3] = f2tf(av1.w);
        Bs[b_n + 0][b_k] = f2tf(bv0.x);
        Bs[b_n + 1][b_k] = f2tf(bv0.y);
        Bs[b_n + 2][b_k] = f2tf(bv0.z);
        Bs[b_n + 3][b_k] = f2tf(bv0.w);
        Bs[b_n + 4][b_k] = f2tf(bv1.x);
        Bs[b_n + 5][b_k] = f2tf(bv1.y);
        Bs[b_n + 6][b_k] = f2tf(bv1.z);
        Bs[b_n + 7][b_k] = f2tf(bv1.w);
        __syncthreads();

        // prefetch next k-tile while mma runs
        if (k0 + 16 < K) {
            av0 = *(const float4*)(pa0 + k0 + 16);
            av1 = *(const float4*)(pa1 + k0 + 16);
            bv0 = *(const float4*)(pb + (size_t)(k0 + 16) * N);
            bv1 = *(const float4*)(pb + (size_t)(k0 + 16) * N + 4);
        }

        #pragma unroll
        for (int kk = 0; kk < 16; kk += 8) {
            uint32_t af[4][4], bf[4][2];
            #pragma unroll
            for (int mt = 0; mt < 4; mt++) {
                int r = warp_m + mt * 16 + lr;
                af[mt][0] = As[r][kk + lc];
                af[mt][1] = As[r + 8][kk + lc];
                af[mt][2] = As[r][kk + 4 + lc];
                af[mt][3] = As[r + 8][kk + 4 + lc];
            }
            #pragma unroll
            for (int nt = 0; nt < 4; nt++) {
                int c = warp_n + nt * 8 + lr;
                bf[nt][0] = Bs[c][kk + lc];
                bf[nt][1] = Bs[c][kk + 4 + lc];
            }
            #pragma unroll
            for (int mt = 0; mt < 4; mt++)
                #pragma unroll
                for (int nt = 0; nt < 4; nt++)
                    mma_tf32(acc[mt][nt], af[mt][0], af[mt][1], af[mt][2], af[mt][3],
                             bf[nt][0], bf[nt][1]);
        }
    }

    // Epilogue: optional bias + optional matrix add + store
    #pragma unroll
    for (int mt = 0; mt < 4; mt++) {
        int row = bm0 + warp_m + mt * 16 + lr;
        #pragma unroll
        for (int nt = 0; nt < 4; nt++) {
            int col = bn0 + warp_n + nt * 8 + lc * 2;
            float b0 = 0.f, b1 = 0.f;
            if (bias) { b0 = bias[col]; b1 = bias[col + 1]; }
            float2 v0 = make_float2(acc[mt][nt][0] + b0, acc[mt][nt][1] + b1);
            float2 v1 = make_float2(acc[mt][nt][2] + b0, acc[mt][nt][3] + b1);
            if (Cadd) {
                float2 c0 = *(const float2*)&Cadd[(size_t)row * N + col];
                float2 c1 = *(const float2*)&Cadd[(size_t)(row + 8) * N + col];
                v0.x += c0.x; v0.y += c0.y;
                v1.x += c1.x; v1.y += c1.y;
            }
            *(float2*)&C[(size_t)row * N + col] = v0;
            *(float2*)&C[(size_t)(row + 8) * N + col] = v1;
        }
    }
}

// ---------------- Tensor-core flash attention (tf32 mma, fp32 softmax) ----------------
#define SP_STRIDE 68
#define KS_STRIDE 68
#define VS_STRIDE 72
#define ATT_SP_OFF   0
#define ATT_KS_OFF   (128*SP_STRIDE)
#define ATT_VS_OFF   (ATT_KS_OFF + 64*KS_STRIDE)
#define ATT_MA_OFF   (ATT_VS_OFF + 64*VS_STRIDE)
#define ATT_FAC_OFF  (ATT_MA_OFF + 64)
#define ATT_SMEM_FLOATS (ATT_FAC_OFF + 128)
#define ATT_SMEM_BYTES  (ATT_SMEM_FLOATS * 4)

extern __shared__ float att_sm[];

__global__ __launch_bounds__(256, 2)
void attn_mma_kernel(const float* __restrict__ qkv, const int* __restrict__ mask,
                     float* __restrict__ out) {
    float*    SP   = att_sm + ATT_SP_OFF;
    float*    Ks   = att_sm + ATT_KS_OFF;
    float*    Vs   = att_sm + ATT_VS_OFF;
    float*    ma   = att_sm + ATT_MA_OFF;
    float*    facs = att_sm + ATT_FAC_OFF;
    uint32_t* SPu  = (uint32_t*)SP;
    uint32_t* Ksu  = (uint32_t*)Ks;
    uint32_t* Vsu  = (uint32_t*)Vs;

    int tid = threadIdx.x, lane = tid & 31, warp = tid >> 5;
    int b = blockIdx.z, h = blockIdx.y;
    int brow = blockIdx.x * 128;
    int g = lane >> 2, tg = lane & 3;
    int wr = warp * 16;
    int row_l = lane >> 1, half = lane & 1;

    // --- stage Q (x SCALE, tf32) into SP ---
    {
        int row = tid >> 1, hf = tid & 1;
        const float* qp = qkv + ((size_t)(b * NN + brow + row)) * (3 * DIMC) + h * DD + hf * 32;
        uint32_t* dst = SPu + row * SP_STRIDE + hf * 32;
        #pragma unroll
        for (int i = 0; i < 8; i++) {
            float4 v = *(const float4*)(qp + i * 4);
            dst[i * 4 + 0] = f2tf(v.x * SCALE_ATT);
            dst[i * 4 + 1] = f2tf(v.y * SCALE_ATT);
            dst[i * 4 + 2] = f2tf(v.z * SCALE_ATT);
            dst[i * 4 + 3] = f2tf(v.w * SCALE_ATT);
        }
    }
    __syncthreads();

    uint32_t aq[8][4];
    #pragma unroll
    for (int kk = 0; kk < 8; kk++) {
        aq[kk][0] = SPu[(wr + g) * SP_STRIDE + kk * 8 + tg];
        aq[kk][1] = SPu[(wr + g + 8) * SP_STRIDE + kk * 8 + tg];
        aq[kk][2] = SPu[(wr + g) * SP_STRIDE + kk * 8 + 4 + tg];
        aq[kk][3] = SPu[(wr + g + 8) * SP_STRIDE + kk * 8 + 4 + tg];
    }

    float o[8][4];
    #pragma unroll
    for (int nt = 0; nt < 8; nt++)
        #pragma unroll
        for (int i = 0; i < 4; i++) o[nt][i] = 0.f;
    float m_run = -1e30f, l_run = 0.f;

    #pragma unroll 1
    for (int t = 0; t < NN / 64; t++) {
        int k0 = t * 64;
        __syncthreads();
        {
            int r = tid >> 2, c4 = (tid & 3) * 16;
            size_t base = ((size_t)(b * NN + k0 + r)) * (3 * DIMC) + h * DD + c4;
            const float* kp = qkv + base + DIMC;
            const float* vp = qkv + base + 2 * DIMC;
            uint32_t* kd = Ksu + r * KS_STRIDE + c4;
            uint32_t* vd = Vsu + r * VS_STRIDE + c4;
            #pragma unroll
            for (int i = 0; i < 4; i++) {
                float4 kv = *(const float4*)(kp + i * 4);
                float4 vv = *(const float4*)(vp + i * 4);
                kd[i * 4 + 0] = f2tf(kv.x);
                kd[i * 4 + 1] = f2tf(kv.y);
                kd[i * 4 + 2] = f2tf(kv.z);
                kd[i * 4 + 3] = f2tf(kv.w);
                vd[i * 4 + 0] = f2tf(vv.x);
                vd[i * 4 + 1] = f2tf(vv.y);
                vd[i * 4 + 2] = f2tf(vv.z);
                vd[i * 4 + 3] = f2tf(vv.w);
            }
            if (tid < 64) ma[tid] = mask[b * NN + k0 + tid] ? 0.f : -1e30f;
        }
        __syncthreads();

        float s[8][4];
        #pragma unroll
        for (int nt = 0; nt < 8; nt++)
            #pragma unroll
            for (int i = 0; i < 4; i++) s[nt][i] = 0.f;
        #pragma unroll
        for (int kk = 0; kk < 8; kk++) {
            #pragma unroll
            for (int nt = 0; nt < 8; nt++) {
                uint32_t b0 = Ksu[(nt * 8 + g) * KS_STRIDE + kk * 8 + tg];
                uint32_t b1 = Ksu[(nt * 8 + g) * KS_STRIDE + kk * 8 + 4 + tg];
                mma_tf32(s[nt], aq[kk][0], aq[kk][1], aq[kk][2], aq[kk][3], b0, b1);
            }
        }
        #pragma unroll
        for (int nt = 0; nt < 8; nt++) {
            *(float2*)&SP[(wr + g) * SP_STRIDE + nt * 8 + 2 * tg]     = make_float2(s[nt][0], s[nt][1]);
            *(float2*)&SP[(wr + g + 8) * SP_STRIDE + nt * 8 + 2 * tg] = make_float2(s[nt][2], s[nt][3]);
        }
        __syncwarp();

        {
            float* srow = SP + (wr + row_l) * SP_STRIDE + half * 32;
            const float* mrow = ma + half * 32;
            float tm = -1e30f;
            #pragma unroll
            for (int j = 0; j < 32; j++) tm = fmaxf(tm, srow[j] + mrow[j]);
            tm = fmaxf(tm, __shfl_xor_sync(0xffffffffu, tm, 1));
            float m_new = fmaxf(m_run, tm);
            float fac = __expf(m_run - m_new);
            float ps = 0.f;
            uint32_t* prow = SPu + (wr + row_l) * SP_STRIDE + half * 32;
            #pragma unroll
            for (int j = 0; j < 32; j++) {
                float p = __expf(srow[j] + mrow[j] - m_new);
                ps += p;
                prow[j] = f2tf(p);
            }
            ps += __shfl_xor_sync(0xffffffffu, ps, 1);
            l_run = l_run * fac + ps;
            m_run = m_new;
            if (half == 0) facs[wr + row_l] = fac;
        }
        __syncwarp();

        float fg  = facs[wr + g];
        float fg8 = facs[wr + g + 8];
        #pragma unroll
        for (int nt = 0; nt < 8; nt++) {
            o[nt][0] *= fg;  o[nt][1] *= fg;
            o[nt][2] *= fg8; o[nt][3] *= fg8;
        }
        #pragma unroll
        for (int kk = 0; kk < 8; kk++) {
            uint32_t a0 = SPu[(wr + g) * SP_STRIDE + kk * 8 + tg];
            uint32_t a1 = SPu[(wr + g + 8) * SP_STRIDE + kk * 8 + tg];
            uint32_t a2 = SPu[(wr + g) * SP_STRIDE + kk * 8 + 4 + tg];
            uint32_t a3 = SPu[(wr + g + 8) * SP_STRIDE + kk * 8 + 4 + tg];
            #pragma unroll
            for (int nt = 0; nt < 8; nt++) {
                uint32_t b0 = Vsu[(kk * 8 + tg) * VS_STRIDE + nt * 8 + g];
                uint32_t b1 = Vsu[(kk * 8 + tg + 4) * VS_STRIDE + nt * 8 + g];
                mma_tf32(o[nt], a0, a1, a2, a3, b0, b1);
            }
        }
    }

    if (half == 0) facs[wr + row_l] = l_run;
    __syncwarp();
    float il  = 1.0f / facs[wr + g];
    float il8 = 1.0f / facs[wr + g + 8];
    size_t r0 = ((size_t)(b * NN + brow + wr + g)) * DIMC + h * DD;
    size_t r8 = ((size_t)(b * NN + brow + wr + g + 8)) * DIMC + h * DD;
    #pragma unroll
    for (int nt = 0; nt < 8; nt++) {
        int col = nt * 8 + 2 * tg;
        *(float2*)&out[r0 + col] = make_float2(o[nt][0] * il,  o[nt][1] * il);
        *(float2*)&out[r8 + col] = make_float2(o[nt][2] * il8, o[nt][3] * il8);
    }
}

// ---------------- Launch ----------------
extern "C" void kernel_launch(void* const* d_in, const int* in_sizes, int n_in,
                              void* d_out, int out_size) {
    const float* x        = (const float*)d_in[0];
    const int*   mask     = (const int*)d_in[1];     // bool marshalled as int32
    const float* qkv_w    = (const float*)d_in[2];
    const float* CP_U_w   = (const float*)d_in[3];
    const float* CP_U_b   = (const float*)d_in[4];
    const float* CP_V_w   = (const float*)d_in[5];
    const float* CP_V_b   = (const float*)d_in[6];
    const float* CP_C     = (const float*)d_in[7];
    const float* CP_att   = (const float*)d_in[8];
    const float* proj_w   = (const float*)d_in[9];
    const float* proj_b   = (const float*)d_in[10];
    float* outp = (float*)d_out;

    float *p_qkv, *p_att, *p_Wbig, *p_Wp, *p_qkvwT, *p_projwT, *p_UwT;
    float *p_Wcq, *p_Wcp, *p_bqc, *p_bpc;
    cudaGetSymbolAddress((void**)&p_qkv,   g_qkv);
    cudaGetSymbolAddress((void**)&p_att,   g_att);
    cudaGetSymbolAddress((void**)&p_Wbig,  g_Wbig);
    cudaGetSymbolAddress((void**)&p_Wp,    g_Wp);
    cudaGetSymbolAddress((void**)&p_qkvwT, g_qkvwT);
    cudaGetSymbolAddress((void**)&p_projwT,g_projwT);
    cudaGetSymbolAddress((void**)&p_UwT,   g_UwT);
    cudaGetSymbolAddress((void**)&p_Wcq,   g_Wcq);
    cudaGetSymbolAddress((void**)&p_Wcp,   g_Wcp);
    cudaGetSymbolAddress((void**)&p_bqc,   g_bqc);
    cudaGetSymbolAddress((void**)&p_bpc,   g_bpc);

    static bool attr_set = false;
    if (!attr_set) {
        cudaFuncSetAttribute(attn_mma_kernel,
                             cudaFuncAttributeMaxDynamicSharedMemorySize, ATT_SMEM_BYTES);
        attr_set = true;
    }

    dim3 tdim(32, 8);
    transpose_kernel<<<dim3(DIMC / 32, (3 * DIMC) / 32), tdim>>>(qkv_w, p_qkvwT, 3 * DIMC, DIMC);
    transpose_kernel<<<dim3(DIMC / 32, DIMC / 32), tdim>>>(proj_w, p_projwT, DIMC, DIMC);
    transpose_kernel<<<dim3(DIMC / 32, RR / 32), tdim>>>(CP_U_w, p_UwT, RR, DIMC);

    cpc_kernel<<<(RR * RR * 4) / 256, 256>>>(CP_C, CP_att);
    wfac_kernel<<<(RR * 2048) / 256, 256>>>(CP_V_w);
    bias_kernel<<<6, 256>>>(CP_V_b, proj_b);
    biascomb_kernel<<<8, 256>>>(CP_U_b);

    // Wcq = qkv_wT + UwT@Wbig   [512,1536]  (K=64)
    gemm_tf32<<<dim3(12, 4), 256>>>(p_UwT, RR, p_Wbig, RR,
                                    nullptr, p_qkvwT, p_Wcq, 3 * DIMC);
    // Wcp = projwT + UwT@Wp     [512,512]   (K=64)
    gemm_tf32<<<dim3(4, 4), 256>>>(p_UwT, RR, p_Wp, RR,
                                   nullptr, p_projwT, p_Wcp, DIMC);

    // qkv = x @ Wcq + bqc       [8192,1536] (K=512)
    gemm_tf32<<<dim3(12, MTOT / 128), 256>>>(x, DIMC, p_Wcq, DIMC,
                                             p_bqc, nullptr, p_qkv, 3 * DIMC);

    // tensor-core flash attention
    attn_mma_kernel<<<dim3(NN / 128, HH, BB), 256, ATT_SMEM_BYTES>>>(p_qkv, mask, p_att);

    // proj = att @ Wcp + bpc    [8192,512]  (K=512)
    gemm_tf32<<<dim3(4, MTOT / 128), 256>>>(p_att, DIMC, p_Wcp, DIMC,
                                            p_bpc, nullptr, outp, DIMC);
}

// round 8
// speedup vs baseline: 3.0980x; 1.2016x over previous
#include <cuda_runtime.h>
#include <cstdint>
#include <cstddef>

// ---------------- Problem constants ----------------
#define BB   8
#define NN   1024
#define DIMC 512
#define HH   8
#define DD   64
#define RR   64          // R1 = R2 = R = 64
#define MTOT (BB*NN)     // 8192
#define SCALE_ATT 0.125f // D^-0.5
#define S_CONST 1.0f

// ---------------- Scratch (__device__ globals; no allocation allowed) ----------------
__device__ float g_qkv  [(size_t)MTOT*3*DIMC];
__device__ float g_att  [(size_t)MTOT*DIMC];
__device__ float g_CPc  [RR*RR*4];
__device__ float g_WbigT[3*DIMC*RR];        // [o][r] o in [0,1536)
__device__ float g_WpT  [DIMC*RR];          // [d][r] (pre-scaled by S)
__device__ float g_Wcq  [(size_t)3*DIMC*DIMC]; // [o][c] = qkv_w + WbigT@CP_U_w
__device__ float g_Wcp  [DIMC*DIMC];           // [o][c] = proj_w + WpT@CP_U_w
__device__ float g_bq   [3*DIMC];           // CP_V_b tiled x3
__device__ float g_bp   [DIMC];             // proj_b + S*CP_V_b
__device__ float g_bqc  [3*DIMC];           // g_bq + CP_U_b@Wbig
__device__ float g_bpc  [DIMC];             // g_bp + CP_U_b@Wp

// ---------------- Small precompute kernels ----------------
__global__ void cpc_kernel(const float* __restrict__ CP_C, const float* __restrict__ CP_att) {
    int idx = blockIdx.x * 256 + threadIdx.x;
    if (idx >= RR * RR * 4) return;
    int f = idx & 3;
    int ij = idx >> 2;
    float s = 0.f;
    #pragma unroll 8
    for (int r = 0; r < RR; r++) s += CP_C[(ij << 6) + r] * CP_att[r * 4 + f];
    g_CPc[idx] = s;
}

// writes W factors TRANSPOSED: WbigT[o][r], WpT[d][r]
__global__ void wfac_kernel(const float* __restrict__ CP_V_w) {
    int idx = blockIdx.x * 256 + threadIdx.x;
    int r = idx >> 11;
    int o = idx & 2047;
    int f, d;
    if (o < 3 * DIMC) { f = o >> 9; d = o & 511; }
    else              { f = 3;      d = o - 3 * DIMC; }
    float s = 0.f;
    #pragma unroll 8
    for (int ss = 0; ss < RR; ss++)
        s += g_CPc[((r << 6) + ss) * 4 + f] * CP_V_w[d * RR + ss];
    if (o < 3 * DIMC) g_WbigT[o * RR + r] = s;
    else              g_WpT[d * RR + r] = s * S_CONST;
}

__global__ void bias_kernel(const float* __restrict__ CP_V_b, const float* __restrict__ proj_b) {
    int i = blockIdx.x * 256 + threadIdx.x;
    if (i < 3 * DIMC) g_bq[i] = CP_V_b[i & 511];
    if (i < DIMC)     g_bp[i] = proj_b[i] + S_CONST * CP_V_b[i];
}

// bias folds: bqc = bq + CP_U_b@Wbig ; bpc = bp + CP_U_b@Wp
__global__ void biascomb_kernel(const float* __restrict__ CP_U_b) {
    int i = blockIdx.x * 256 + threadIdx.x;   // 2048 total
    if (i < 3 * DIMC) {
        float s = g_bq[i];
        #pragma unroll 8
        for (int r = 0; r < RR; r++) s += CP_U_b[r] * g_WbigT[i * RR + r];
        g_bqc[i] = s;
    } else if (i < 3 * DIMC + DIMC) {
        int d = i - 3 * DIMC;
        float s = g_bp[d];
        #pragma unroll 8
        for (int r = 0; r < RR; r++) s += CP_U_b[r] * g_WpT[d * RR + r];
        g_bpc[d] = s;
    }
}

// ---------------- tf32 helpers ----------------
__device__ __forceinline__ uint32_t f2tf(float x) {
    uint32_t r;
    asm("cvt.rna.tf32.f32 %0, %1;" : "=r"(r) : "f"(x));
    return r;
}

__device__ __forceinline__ void mma_tf32(float c[4], uint32_t a0, uint32_t a1,
                                         uint32_t a2, uint32_t a3,
                                         uint32_t b0, uint32_t b1) {
    asm volatile(
        "mma.sync.aligned.m16n8k8.row.col.f32.tf32.tf32.f32 "
        "{%0,%1,%2,%3}, {%4,%5,%6,%7}, {%8,%9}, {%0,%1,%2,%3};\n"
        : "+f"(c[0]), "+f"(c[1]), "+f"(c[2]), "+f"(c[3])
        : "r"(a0), "r"(a1), "r"(a2), "r"(a3), "r"(b0), "r"(b1));
}

// ---------------- Double-buffered tf32 GEMM ----------------
// C[M,N] = A[M,K]@B (+ bias[N]) (+ Cadd[M,N])
// BNK=1: B stored [N,K] row-major (weights). BNK=0: B stored [K,N] row-major.
// M,N multiples of 128; K multiple of 16. BM=BN=128, BK=16, 256 thr (8 warps),
// warp tile 64x32, mma m16n8k8 tf32. Double-buffered smem, 1 sync per k-tile.
template<int BNK>
__global__ __launch_bounds__(256)
void gemm_tf32(const float* __restrict__ A, int lda,
               const float* __restrict__ B, int K,
               const float* __restrict__ bias, const float* __restrict__ Cadd,
               float* __restrict__ C, int N) {
    __shared__ uint32_t As[2][128][20];
    __shared__ uint32_t Bs[2][128][20];

    int tid  = threadIdx.x;
    int lane = tid & 31;
    int warp = tid >> 5;
    int warp_m = (warp >> 2) * 64;
    int warp_n = (warp & 3) * 32;
    int bm0 = blockIdx.y * 128;
    int bn0 = blockIdx.x * 128;
    int lr = lane >> 2;
    int lc = lane & 3;

    float acc[4][4][4];
    #pragma unroll
    for (int i = 0; i < 4; i++)
        #pragma unroll
        for (int j = 0; j < 4; j++)
            #pragma unroll
            for (int k = 0; k < 4; k++) acc[i][j][k] = 0.f;

    // A loader: rows a_m, a_m+64; k offset a_k
    int a_m = tid >> 2;                // 0..63
    int a_k = (tid & 3) * 4;           // 0,4,8,12
    const float* pa0 = &A[(size_t)(bm0 + a_m) * lda + a_k];
    const float* pa1 = &A[(size_t)(bm0 + a_m + 64) * lda + a_k];

    // B loader
    int bkn_k = tid >> 4;              // KN: 0..15
    int bkn_n = (tid & 15) * 8;        // KN: 0..120
    int bnk_n = tid >> 1;              // NK: 0..127
    int bnk_k = (tid & 1) * 8;         // NK: 0 or 8
    const float* pb_kn = &B[(size_t)bkn_k * N + bn0 + bkn_n];
    const float* pb_nk = &B[(size_t)(bn0 + bnk_n) * K + bnk_k];

    float4 av0, av1, bv0, bv1;

    // ---- prologue: load + store tile 0 ----
    av0 = *(const float4*)pa0;
    av1 = *(const float4*)pa1;
    if (BNK) {
        bv0 = *(const float4*)pb_nk;
        bv1 = *(const float4*)(pb_nk + 4);
    } else {
        bv0 = *(const float4*)pb_kn;
        bv1 = *(const float4*)(pb_kn + 4);
    }
    {
        uint4 wa0 = make_uint4(f2tf(av0.x), f2tf(av0.y), f2tf(av0.z), f2tf(av0.w));
        uint4 wa1 = make_uint4(f2tf(av1.x), f2tf(av1.y), f2tf(av1.z), f2tf(av1.w));
        *(uint4*)&As[0][a_m][a_k]      = wa0;
        *(uint4*)&As[0][a_m + 64][a_k] = wa1;
        if (BNK) {
            uint4 wb0 = make_uint4(f2tf(bv0.x), f2tf(bv0.y), f2tf(bv0.z), f2tf(bv0.w));
            uint4 wb1 = make_uint4(f2tf(bv1.x), f2tf(bv1.y), f2tf(bv1.z), f2tf(bv1.w));
            *(uint4*)&Bs[0][bnk_n][bnk_k]     = wb0;
            *(uint4*)&Bs[0][bnk_n][bnk_k + 4] = wb1;
        } else {
            Bs[0][bkn_n + 0][bkn_k] = f2tf(bv0.x);
            Bs[0][bkn_n + 1][bkn_k] = f2tf(bv0.y);
            Bs[0][bkn_n + 2][bkn_k] = f2tf(bv0.z);
            Bs[0][bkn_n + 3][bkn_k] = f2tf(bv0.w);
            Bs[0][bkn_n + 4][bkn_k] = f2tf(bv1.x);
            Bs[0][bkn_n + 5][bkn_k] = f2tf(bv1.y);
            Bs[0][bkn_n + 6][bkn_k] = f2tf(bv1.z);
            Bs[0][bkn_n + 7][bkn_k] = f2tf(bv1.w);
        }
    }
    __syncthreads();

    int T = K / 16;
    #pragma unroll 1
    for (int t = 0; t < T; t++) {
        int p = t & 1;
        // prefetch next tile (LDG) — hides under mma stage below
        if (t + 1 < T) {
            int k0 = (t + 1) * 16;
            av0 = *(const float4*)(pa0 + k0);
            av1 = *(const float4*)(pa1 + k0);
            if (BNK) {
                bv0 = *(const float4*)(pb_nk + k0);
                bv1 = *(const float4*)(pb_nk + k0 + 4);
            } else {
                bv0 = *(const float4*)(pb_kn + (size_t)k0 * N);
                bv1 = *(const float4*)(pb_kn + (size_t)k0 * N + 4);
            }
        }

        // ---- mma on buffer p ----
        #pragma unroll
        for (int kk = 0; kk < 16; kk += 8) {
            uint32_t af[4][4], bf[4][2];
            #pragma unroll
            for (int mt = 0; mt < 4; mt++) {
                int r = warp_m + mt * 16 + lr;
                af[mt][0] = As[p][r][kk + lc];
                af[mt][1] = As[p][r + 8][kk + lc];
                af[mt][2] = As[p][r][kk + 4 + lc];
                af[mt][3] = As[p][r + 8][kk + 4 + lc];
            }
            #pragma unroll
            for (int nt = 0; nt < 4; nt++) {
                int c = warp_n + nt * 8 + lr;
                bf[nt][0] = Bs[p][c][kk + lc];
                bf[nt][1] = Bs[p][c][kk + 4 + lc];
            }
            #pragma unroll
            for (int mt = 0; mt < 4; mt++)
                #pragma unroll
                for (int nt = 0; nt < 4; nt++)
                    mma_tf32(acc[mt][nt], af[mt][0], af[mt][1], af[mt][2], af[mt][3],
                             bf[nt][0], bf[nt][1]);
        }

        // ---- store next tile into the other buffer ----
        if (t + 1 < T) {
            int q = 1 - p;
            uint4 wa0 = make_uint4(f2tf(av0.x), f2tf(av0.y), f2tf(av0.z), f2tf(av0.w));
            uint4 wa1 = make_uint4(f2tf(av1.x), f2tf(av1.y), f2tf(av1.z), f2tf(av1.w));
            *(uint4*)&As[q][a_m][a_k]      = wa0;
            *(uint4*)&As[q][a_m + 64][a_k] = wa1;
            if (BNK) {
                uint4 wb0 = make_uint4(f2tf(bv0.x), f2tf(bv0.y), f2tf(bv0.z), f2tf(bv0.w));
                uint4 wb1 = make_uint4(f2tf(bv1.x), f2tf(bv1.y), f2tf(bv1.z), f2tf(bv1.w));
                *(uint4*)&Bs[q][bnk_n][bnk_k]     = wb0;
                *(uint4*)&Bs[q][bnk_n][bnk_k + 4] = wb1;
            } else {
                Bs[q][bkn_n + 0][bkn_k] = f2tf(bv0.x);
                Bs[q][bkn_n + 1][bkn_k] = f2tf(bv0.y);
                Bs[q][bkn_n + 2][bkn_k] = f2tf(bv0.z);
                Bs[q][bkn_n + 3][bkn_k] = f2tf(bv0.w);
                Bs[q][bkn_n + 4][bkn_k] = f2tf(bv1.x);
                Bs[q][bkn_n + 5][bkn_k] = f2tf(bv1.y);
                Bs[q][bkn_n + 6][bkn_k] = f2tf(bv1.z);
                Bs[q][bkn_n + 7][bkn_k] = f2tf(bv1.w);
            }
        }
        __syncthreads();
    }

    // Epilogue: optional bias + optional matrix add + store
    #pragma unroll
    for (int mt = 0; mt < 4; mt++) {
        int row = bm0 + warp_m + mt * 16 + lr;
        #pragma unroll
        for (int nt = 0; nt < 4; nt++) {
            int col = bn0 + warp_n + nt * 8 + lc * 2;
            float b0 = 0.f, b1 = 0.f;
            if (bias) { b0 = bias[col]; b1 = bias[col + 1]; }
            float2 v0 = make_float2(acc[mt][nt][0] + b0, acc[mt][nt][1] + b1);
            float2 v1 = make_float2(acc[mt][nt][2] + b0, acc[mt][nt][3] + b1);
            if (Cadd) {
                float2 c0 = *(const float2*)&Cadd[(size_t)row * N + col];
                float2 c1 = *(const float2*)&Cadd[(size_t)(row + 8) * N + col];
                v0.x += c0.x; v0.y += c0.y;
                v1.x += c1.x; v1.y += c1.y;
            }
            *(float2*)&C[(size_t)row * N + col] = v0;
            *(float2*)&C[(size_t)(row + 8) * N + col] = v1;
        }
    }
}

// ---------------- Tensor-core flash attention (tf32 mma, fp32 softmax) ----------------
#define SP_STRIDE 68
#define KS_STRIDE 68
#define VS_STRIDE 72
#define ATT_SP_OFF   0
#define ATT_KS_OFF   (128*SP_STRIDE)
#define ATT_VS_OFF   (ATT_KS_OFF + 64*KS_STRIDE)
#define ATT_MA_OFF   (ATT_VS_OFF + 64*VS_STRIDE)
#define ATT_FAC_OFF  (ATT_MA_OFF + 64)
#define ATT_SMEM_FLOATS (ATT_FAC_OFF + 128)
#define ATT_SMEM_BYTES  (ATT_SMEM_FLOATS * 4)

extern __shared__ float att_sm[];

__global__ __launch_bounds__(256, 2)
void attn_mma_kernel(const float* __restrict__ qkv, const int* __restrict__ mask,
                     float* __restrict__ out) {
    float*    SP   = att_sm + ATT_SP_OFF;
    float*    Ks   = att_sm + ATT_KS_OFF;
    float*    Vs   = att_sm + ATT_VS_OFF;
    float*    ma   = att_sm + ATT_MA_OFF;
    float*    facs = att_sm + ATT_FAC_OFF;
    uint32_t* SPu  = (uint32_t*)SP;
    uint32_t* Ksu  = (uint32_t*)Ks;
    uint32_t* Vsu  = (uint32_t*)Vs;

    int tid = threadIdx.x, lane = tid & 31, warp = tid >> 5;
    int b = blockIdx.z, h = blockIdx.y;
    int brow = blockIdx.x * 128;
    int g = lane >> 2, tg = lane & 3;
    int wr = warp * 16;
    int row_l = lane >> 1, half = lane & 1;

    {
        int row = tid >> 1, hf = tid & 1;
        const float* qp = qkv + ((size_t)(b * NN + brow + row)) * (3 * DIMC) + h * DD + hf * 32;
        uint32_t* dst = SPu + row * SP_STRIDE + hf * 32;
        #pragma unroll
        for (int i = 0; i < 8; i++) {
            float4 v = *(const float4*)(qp + i * 4);
            dst[i * 4 + 0] = f2tf(v.x * SCALE_ATT);
            dst[i * 4 + 1] = f2tf(v.y * SCALE_ATT);
            dst[i * 4 + 2] = f2tf(v.z * SCALE_ATT);
            dst[i * 4 + 3] = f2tf(v.w * SCALE_ATT);
        }
    }
    __syncthreads();

    uint32_t aq[8][4];
    #pragma unroll
    for (int kk = 0; kk < 8; kk++) {
        aq[kk][0] = SPu[(wr + g) * SP_STRIDE + kk * 8 + tg];
        aq[kk][1] = SPu[(wr + g + 8) * SP_STRIDE + kk * 8 + tg];
        aq[kk][2] = SPu[(wr + g) * SP_STRIDE + kk * 8 + 4 + tg];
        aq[kk][3] = SPu[(wr + g + 8) * SP_STRIDE + kk * 8 + 4 + tg];
    }

    float o[8][4];
    #pragma unroll
    for (int nt = 0; nt < 8; nt++)
        #pragma unroll
        for (int i = 0; i < 4; i++) o[nt][i] = 0.f;
    float m_run = -1e30f, l_run = 0.f;

    #pragma unroll 1
    for (int t = 0; t < NN / 64; t++) {
        int k0 = t * 64;
        __syncthreads();
        {
            int r = tid >> 2, c4 = (tid & 3) * 16;
            size_t base = ((size_t)(b * NN + k0 + r)) * (3 * DIMC) + h * DD + c4;
            const float* kp = qkv + base + DIMC;
            const float* vp = qkv + base + 2 * DIMC;
            uint32_t* kd = Ksu + r * KS_STRIDE + c4;
            uint32_t* vd = Vsu + r * VS_STRIDE + c4;
            #pragma unroll
            for (int i = 0; i < 4; i++) {
                float4 kv = *(const float4*)(kp + i * 4);
                float4 vv = *(const float4*)(vp + i * 4);
                kd[i * 4 + 0] = f2tf(kv.x);
                kd[i * 4 + 1] = f2tf(kv.y);
                kd[i * 4 + 2] = f2tf(kv.z);
                kd[i * 4 + 3] = f2tf(kv.w);
                vd[i * 4 + 0] = f2tf(vv.x);
                vd[i * 4 + 1] = f2tf(vv.y);
                vd[i * 4 + 2] = f2tf(vv.z);
                vd[i * 4 + 3] = f2tf(vv.w);
            }
            if (tid < 64) ma[tid] = mask[b * NN + k0 + tid] ? 0.f : -1e30f;
        }
        __syncthreads();

        float s[8][4];
        #pragma unroll
        for (int nt = 0; nt < 8; nt++)
            #pragma unroll
            for (int i = 0; i < 4; i++) s[nt][i] = 0.f;
        #pragma unroll
        for (int kk = 0; kk < 8; kk++) {
            #pragma unroll
            for (int nt = 0; nt < 8; nt++) {
                uint32_t b0 = Ksu[(nt * 8 + g) * KS_STRIDE + kk * 8 + tg];
                uint32_t b1 = Ksu[(nt * 8 + g) * KS_STRIDE + kk * 8 + 4 + tg];
                mma_tf32(s[nt], aq[kk][0], aq[kk][1], aq[kk][2], aq[kk][3], b0, b1);
            }
        }
        #pragma unroll
        for (int nt = 0; nt < 8; nt++) {
            *(float2*)&SP[(wr + g) * SP_STRIDE + nt * 8 + 2 * tg]     = make_float2(s[nt][0], s[nt][1]);
            *(float2*)&SP[(wr + g + 8) * SP_STRIDE + nt * 8 + 2 * tg] = make_float2(s[nt][2], s[nt][3]);
        }
        __syncwarp();

        {
            float* srow = SP + (wr + row_l) * SP_STRIDE + half * 32;
            const float* mrow = ma + half * 32;
            float tm = -1e30f;
            #pragma unroll
            for (int j = 0; j < 32; j++) tm = fmaxf(tm, srow[j] + mrow[j]);
            tm = fmaxf(tm, __shfl_xor_sync(0xffffffffu, tm, 1));
            float m_new = fmaxf(m_run, tm);
            float fac = __expf(m_run - m_new);
            float ps = 0.f;
            uint32_t* prow = SPu + (wr + row_l) * SP_STRIDE + half * 32;
            #pragma unroll
            for (int j = 0; j < 32; j++) {
                float p = __expf(srow[j] + mrow[j] - m_new);
                ps += p;
                prow[j] = f2tf(p);
            }
            ps += __shfl_xor_sync(0xffffffffu, ps, 1);
            l_run = l_run * fac + ps;
            m_run = m_new;
            if (half == 0) facs[wr + row_l] = fac;
        }
        __syncwarp();

        float fg  = facs[wr + g];
        float fg8 = facs[wr + g + 8];
        #pragma unroll
        for (int nt = 0; nt < 8; nt++) {
            o[nt][0] *= fg;  o[nt][1] *= fg;
            o[nt][2] *= fg8; o[nt][3] *= fg8;
        }
        #pragma unroll
        for (int kk = 0; kk < 8; kk++) {
            uint32_t a0 = SPu[(wr + g) * SP_STRIDE + kk * 8 + tg];
            uint32_t a1 = SPu[(wr + g + 8) * SP_STRIDE + kk * 8 + tg];
            uint32_t a2 = SPu[(wr + g) * SP_STRIDE + kk * 8 + 4 + tg];
            uint32_t a3 = SPu[(wr + g + 8) * SP_STRIDE + kk * 8 + 4 + tg];
            #pragma unroll
            for (int nt = 0; nt < 8; nt++) {
                uint32_t b0 = Vsu[(kk * 8 + tg) * VS_STRIDE + nt * 8 + g];
                uint32_t b1 = Vsu[(kk * 8 + tg + 4) * VS_STRIDE + nt * 8 + g];
                mma_tf32(o[nt], a0, a1, a2, a3, b0, b1);
            }
        }
    }

    if (half == 0) facs[wr + row_l] = l_run;
    __syncwarp();
    float il  = 1.0f / facs[wr + g];
    float il8 = 1.0f / facs[wr + g + 8];
    size_t r0 = ((size_t)(b * NN + brow + wr + g)) * DIMC + h * DD;
    size_t r8 = ((size_t)(b * NN + brow + wr + g + 8)) * DIMC + h * DD;
    #pragma unroll
    for (int nt = 0; nt < 8; nt++) {
        int col = nt * 8 + 2 * tg;
        *(float2*)&out[r0 + col] = make_float2(o[nt][0] * il,  o[nt][1] * il);
        *(float2*)&out[r8 + col] = make_float2(o[nt][2] * il8, o[nt][3] * il8);
    }
}

// ---------------- Launch ----------------
extern "C" void kernel_launch(void* const* d_in, const int* in_sizes, int n_in,
                              void* d_out, int out_size) {
    const float* x        = (const float*)d_in[0];
    const int*   mask     = (const int*)d_in[1];     // bool marshalled as int32
    const float* qkv_w    = (const float*)d_in[2];
    const float* CP_U_w   = (const float*)d_in[3];
    const float* CP_U_b   = (const float*)d_in[4];
    const float* CP_V_w   = (const float*)d_in[5];
    const float* CP_V_b   = (const float*)d_in[6];
    const float* CP_C     = (const float*)d_in[7];
    const float* CP_att   = (const float*)d_in[8];
    const float* proj_w   = (const float*)d_in[9];
    const float* proj_b   = (const float*)d_in[10];
    float* outp = (float*)d_out;

    float *p_qkv, *p_att, *p_WbigT, *p_WpT, *p_Wcq, *p_Wcp, *p_bqc, *p_bpc;
    cudaGetSymbolAddress((void**)&p_qkv,   g_qkv);
    cudaGetSymbolAddress((void**)&p_att,   g_att);
    cudaGetSymbolAddress((void**)&p_WbigT, g_WbigT);
    cudaGetSymbolAddress((void**)&p_WpT,   g_WpT);
    cudaGetSymbolAddress((void**)&p_Wcq,   g_Wcq);
    cudaGetSymbolAddress((void**)&p_Wcp,   g_Wcp);
    cudaGetSymbolAddress((void**)&p_bqc,   g_bqc);
    cudaGetSymbolAddress((void**)&p_bpc,   g_bpc);

    static bool attr_set = false;
    if (!attr_set) {
        cudaFuncSetAttribute(attn_mma_kernel,
                             cudaFuncAttributeMaxDynamicSharedMemorySize, ATT_SMEM_BYTES);
        attr_set = true;
    }

    cpc_kernel<<<(RR * RR * 4) / 256, 256>>>(CP_C, CP_att);
    wfac_kernel<<<(RR * 2048) / 256, 256>>>(CP_V_w);
    bias_kernel<<<6, 256>>>(CP_V_b, proj_b);
    biascomb_kernel<<<8, 256>>>(CP_U_b);

    // Wcq[o][c] = qkv_w[o][c] + (WbigT @ CP_U_w)[o][c]   [1536,512], K=64
    gemm_tf32<0><<<dim3(4, 12), 256>>>(p_WbigT, RR, CP_U_w, RR,
                                       nullptr, qkv_w, p_Wcq, DIMC);
    // Wcp[o][c] = proj_w[o][c] + (WpT @ CP_U_w)[o][c]    [512,512],  K=64
    gemm_tf32<0><<<dim3(4, 4), 256>>>(p_WpT, RR, CP_U_w, RR,
                                      nullptr, proj_w, p_Wcp, DIMC);

    // qkv = x @ Wcq^T + bqc     [8192,1536], K=512, B in [N,K]
    gemm_tf32<1><<<dim3(12, MTOT / 128), 256>>>(x, DIMC, p_Wcq, DIMC,
                                                p_bqc, nullptr, p_qkv, 3 * DIMC);

    // tensor-core flash attention
    attn_mma_kernel<<<dim3(NN / 128, HH, BB), 256, ATT_SMEM_BYTES>>>(p_qkv, mask, p_att);

    // proj = att @ Wcp^T + bpc  [8192,512], K=512, B in [N,K]
    gemm_tf32<1><<<dim3(4, MTOT / 128), 256>>>(p_att, DIMC, p_Wcp, DIMC,
                                               p_bpc, nullptr, outp, DIMC);
}